// round 5
// baseline (speedup 1.0000x reference)
#include <cuda_runtime.h>
#include <cstdint>

// Problem constants (fixed by setup_inputs)
#define Bb    2
#define Tt    2048
#define Cc    1024
#define QLd   128
#define KVL   128
#define NHh   16
#define HSd   64
#define BT    (Bb*Tt)          // 4096

// Scratch (device globals: no allocation allowed)
__device__ float g_P [QLd*KVL];          // W_uq^T @ W_uk          (128,128)
__device__ float g_M [Cc*KVL];           // W_dq^T @ P             (1024,128)
__device__ float g_Nt[NHh*KVL*QLd];      // Nt[h][j][i] = N[h][i][j]
__device__ float g_R [Cc*KVL];           // W_o @ W_uv             (1024,128)
__device__ float g_Aq[BT*QLd];           // x @ W_dq^T             (4096,128)
__device__ float g_ql[NHh*BT*KVL];       // latent queries         (16,4096,128)
__device__ float g_ct[NHh*BT*KVL];       // latent context         (16,4096,128)

__device__ __forceinline__ uint32_t f2tf(float f) {
    uint32_t u;
    asm("cvt.rna.tf32.f32 %0, %1;" : "=r"(u) : "f"(f));
    return u;
}
__device__ __forceinline__ void mma_tf32(float* d, const uint32_t* a, const uint32_t* b) {
    asm volatile(
        "mma.sync.aligned.m16n8k8.row.col.f32.tf32.tf32.f32 "
        "{%0,%1,%2,%3}, {%4,%5,%6,%7}, {%8,%9}, {%0,%1,%2,%3};"
        : "+f"(d[0]), "+f"(d[1]), "+f"(d[2]), "+f"(d[3])
        : "r"(a[0]), "r"(a[1]), "r"(a[2]), "r"(a[3]), "r"(b[0]), "r"(b[1]));
}

// ===========================================================================
// tf32 tensor-core GEMM (unchanged from R4)
// ===========================================================================
template<int BN, bool NN, bool COMP>
__global__ __launch_bounds__(256)
void tgemm(const float* __restrict__ A, const float* __restrict__ B,
           float* __restrict__ C, const float* __restrict__ B2,
           float* __restrict__ C2, int K,
           int lda, int ldb, int ldc, long sA, long sB, long sC, int nb1)
{
    constexpr int BM = 128, AW = BM * 20, BW = BN * 20;
    constexpr int NF = BN / 16;
    extern __shared__ uint32_t sh[];
    uint32_t* Ah = sh;
    uint32_t* Bh = sh + AW;
    uint32_t* Al = sh + AW + BW;
    uint32_t* Bl = sh + 2 * AW + BW;

    const int z = blockIdx.z;
    A += (long)z * sA;
    const float* Bp = B;  float* Cp = C;
    int by = blockIdx.y;
    if (by >= nb1) { Bp = B2; Cp = C2; by -= nb1; }
    Bp += (long)z * sB;  Cp += (long)z * sC;

    const int m0 = blockIdx.x * BM, n0 = by * BN;
    const int t = threadIdx.x;
    const int wid = t >> 5, g = (t & 31) >> 2, tid = t & 3;
    const int wm = wid >> 1, wn = wid & 1;

    float acc[2][NF][4];
    #pragma unroll
    for (int i = 0; i < 2; i++)
        #pragma unroll
        for (int j = 0; j < NF; j++)
            #pragma unroll
            for (int q = 0; q < 4; q++) acc[i][j][q] = 0.f;

    for (int k0 = 0; k0 < K; k0 += 16) {
        #pragma unroll
        for (int i = 0; i < 2; i++) {
            int idx = t + i * 256;
            int r = idx >> 2, cg = (idx & 3) * 4;
            float4 v = *(const float4*)(A + (long)(m0 + r) * lda + k0 + cg);
            uint4 h; h.x = f2tf(v.x); h.y = f2tf(v.y); h.z = f2tf(v.z); h.w = f2tf(v.w);
            *(uint4*)(Ah + r * 20 + cg) = h;
            if (COMP) {
                uint4 l;
                l.x = f2tf(v.x - __uint_as_float(h.x));
                l.y = f2tf(v.y - __uint_as_float(h.y));
                l.z = f2tf(v.z - __uint_as_float(h.z));
                l.w = f2tf(v.w - __uint_as_float(h.w));
                *(uint4*)(Al + r * 20 + cg) = l;
            }
        }
        if (!NN) {
            #pragma unroll
            for (int i = 0; i < BN / 64; i++) {
                int idx = t + i * 256;
                int r = idx >> 2, cg = (idx & 3) * 4;
                float4 v = *(const float4*)(Bp + (long)(n0 + r) * ldb + k0 + cg);
                uint4 h; h.x = f2tf(v.x); h.y = f2tf(v.y); h.z = f2tf(v.z); h.w = f2tf(v.w);
                *(uint4*)(Bh + r * 20 + cg) = h;
                if (COMP) {
                    uint4 l;
                    l.x = f2tf(v.x - __uint_as_float(h.x));
                    l.y = f2tf(v.y - __uint_as_float(h.y));
                    l.z = f2tf(v.z - __uint_as_float(h.z));
                    l.w = f2tf(v.w - __uint_as_float(h.w));
                    *(uint4*)(Bl + r * 20 + cg) = l;
                }
            }
        } else {
            #pragma unroll
            for (int i = 0; i < BN / 64; i++) {
                int idx = t + i * 256;
                int kr = idx >> (BN == 64 ? 4 : 5);
                int nn = (idx & (BN / 4 - 1)) * 4;
                float4 v = *(const float4*)(Bp + (long)(k0 + kr) * ldb + n0 + nn);
                Bh[(nn + 0) * 20 + kr] = f2tf(v.x);
                Bh[(nn + 1) * 20 + kr] = f2tf(v.y);
                Bh[(nn + 2) * 20 + kr] = f2tf(v.z);
                Bh[(nn + 3) * 20 + kr] = f2tf(v.w);
            }
        }
        __syncthreads();

        #pragma unroll
        for (int s = 0; s < 2; s++) {
            const int kk = 8 * s + tid;
            uint32_t ah[2][4], al[2][4];
            #pragma unroll
            for (int mf = 0; mf < 2; mf++) {
                int r = wm * 32 + 16 * mf + g;
                ah[mf][0] = Ah[r * 20 + kk];       ah[mf][1] = Ah[(r + 8) * 20 + kk];
                ah[mf][2] = Ah[r * 20 + kk + 4];   ah[mf][3] = Ah[(r + 8) * 20 + kk + 4];
                if (COMP) {
                    al[mf][0] = Al[r * 20 + kk];     al[mf][1] = Al[(r + 8) * 20 + kk];
                    al[mf][2] = Al[r * 20 + kk + 4]; al[mf][3] = Al[(r + 8) * 20 + kk + 4];
                }
            }
            uint32_t bh[NF][2], bl[NF][2];
            #pragma unroll
            for (int nf = 0; nf < NF; nf++) {
                int n = wn * (BN / 2) + 8 * nf + g;
                bh[nf][0] = Bh[n * 20 + kk];  bh[nf][1] = Bh[n * 20 + kk + 4];
                if (COMP) { bl[nf][0] = Bl[n * 20 + kk]; bl[nf][1] = Bl[n * 20 + kk + 4]; }
            }
            #pragma unroll
            for (int mf = 0; mf < 2; mf++)
                #pragma unroll
                for (int nf = 0; nf < NF; nf++) {
                    mma_tf32(acc[mf][nf], ah[mf], bh[nf]);
                    if (COMP) {
                        mma_tf32(acc[mf][nf], ah[mf], bl[nf]);
                        mma_tf32(acc[mf][nf], al[mf], bh[nf]);
                    }
                }
        }
        __syncthreads();
    }

    #pragma unroll
    for (int mf = 0; mf < 2; mf++) {
        const int r0 = m0 + wm * 32 + 16 * mf + g;
        #pragma unroll
        for (int nf = 0; nf < NF; nf++) {
            const int c = n0 + wn * (BN / 2) + 8 * nf + 2 * tid;
            *(float2*)(Cp + (long)r0 * ldc + c)       = make_float2(acc[mf][nf][0], acc[mf][nf][1]);
            *(float2*)(Cp + (long)(r0 + 8) * ldc + c) = make_float2(acc[mf][nf][2], acc[mf][nf][3]);
        }
    }
}

// ===========================================================================
// Tiny fp32-exact precompute kernels
// ===========================================================================
// P[i,j] = sum_c W_uq[c,i] * W_uk[c,j]
__global__ __launch_bounds__(128)
void pk_kernel(const float* __restrict__ W_uq, const float* __restrict__ W_uk,
               float* __restrict__ P)
{
    const int i = blockIdx.x, j = threadIdx.x;
    float s = 0.f;
    #pragma unroll 8
    for (int c = 0; c < 1024; c++)
        s += W_uq[c * 128 + i] * W_uk[c * 128 + j];
    P[i * 128 + j] = s;
}
// M[c,j] = sum_i W_dq[i,c] * P[i,j]
__global__ __launch_bounds__(128)
void m_kernel(const float* __restrict__ W_dq, const float* __restrict__ P,
              float* __restrict__ M)
{
    const int c = blockIdx.x, j = threadIdx.x;
    float s = 0.f;
    #pragma unroll 8
    for (int i = 0; i < 128; i++)
        s += W_dq[i * 1024 + c] * P[i * 128 + j];
    M[c * 128 + j] = s;
}
// Nt[h][j][i] = N[h][i][j] = sum_d W_uq[h*64+d, i] * M[h*64+d, j]
__global__ __launch_bounds__(128)
void n_kernel(const float* __restrict__ W_uq, const float* __restrict__ M,
              float* __restrict__ Nt)
{
    const int j = blockIdx.x, h = blockIdx.y, i = threadIdx.x;
    float s = 0.f;
    #pragma unroll 8
    for (int d = 0; d < 64; d++)
        s += W_uq[(h * 64 + d) * 128 + i] * M[(h * 64 + d) * 128 + j];
    Nt[(h * 128 + j) * 128 + i] = s;
}

// ===========================================================================
// mma.sync tf32 flash attention v2.
// CTA: 64 queries, 2 warps (64 threads), each warp 32 rows (mf=2).
// Single K copy (LD=132): S-phase conflict-free, PV 2-way (crossbar headroom).
// 85 KB smem -> 2 CTAs/SM so load/softmax phases overlap across CTAs.
// ===========================================================================
#define AT_QS 0              // 64 x 132
#define AT_K  8448           // 64 x 132
#define AT_PS 16896          // 64 x 68
#define AT_WORDS 21248       // 84992 bytes

__global__ __launch_bounds__(64, 2)
void attn2_kernel(const float* __restrict__ ql, const float* __restrict__ ckv,
                  float* __restrict__ ctx)
{
    extern __shared__ uint32_t smu[];
    const int t = threadIdx.x;
    const int w = t >> 5, lid = t & 31;
    const int g = lid >> 2, tid = lid & 3;

    const int qt = 31 - blockIdx.x;          // heavy tiles first
    const int bh = blockIdx.y;
    const int b = bh >> 4, h = bh & 15;
    const long qbase = ((long)h * BT + (long)b * Tt + (long)qt * 64) * 128;
    const long kbase = (long)b * Tt * 128;

    // Q tile: 64x128, prescaled by 1/8, tf32
    {
        const float* qs = ql + qbase;
        #pragma unroll
        for (int i = 0; i < 32; i++) {
            int idx = t + i * 64;
            int r = idx >> 5, c = (idx & 31) * 4;
            float4 v = *(const float4*)(qs + (long)r * 128 + c);
            uint4 u;
            u.x = f2tf(v.x * 0.125f); u.y = f2tf(v.y * 0.125f);
            u.z = f2tf(v.z * 0.125f); u.w = f2tf(v.w * 0.125f);
            *(uint4*)(smu + AT_QS + r * 132 + c) = u;
        }
    }

    float oacc[2][16][4];
    #pragma unroll
    for (int mf = 0; mf < 2; mf++)
        #pragma unroll
        for (int nb = 0; nb < 16; nb++)
            #pragma unroll
            for (int q = 0; q < 4; q++) oacc[mf][nb][q] = 0.f;

    float m_run[2][2] = {{-1e30f, -1e30f}, {-1e30f, -1e30f}};
    float l_run[2][2] = {{0.f, 0.f}, {0.f, 0.f}};

    for (int kt = 0; kt <= qt; kt++) {
        __syncthreads();     // prev PV reads of K done (iter 0: also Q store fence... Q is read after too)
        {
            const float* ks = ckv + kbase + (long)kt * 64 * 128;
            #pragma unroll
            for (int i = 0; i < 32; i++) {
                int idx = t + i * 64;
                int r = idx >> 5, c = (idx & 31) * 4;
                float4 v = *(const float4*)(ks + (long)r * 128 + c);
                uint4 u;
                u.x = f2tf(v.x); u.y = f2tf(v.y); u.z = f2tf(v.z); u.w = f2tf(v.w);
                *(uint4*)(smu + AT_K + r * 132 + c) = u;
            }
        }
        __syncthreads();

        // ---- S = Q K^T : 16 k-steps over d; 8 key-blocks; 2 m-frags ----
        float sacc[2][8][4];
        #pragma unroll
        for (int mf = 0; mf < 2; mf++)
            #pragma unroll
            for (int nb = 0; nb < 8; nb++)
                #pragma unroll
                for (int q = 0; q < 4; q++) sacc[mf][nb][q] = 0.f;

        #pragma unroll
        for (int ks = 0; ks < 16; ks++) {
            const int d0 = 8 * ks + tid;
            uint32_t af[2][4];
            #pragma unroll
            for (int mf = 0; mf < 2; mf++) {
                const int r = 32 * w + 16 * mf + g;
                af[mf][0] = smu[AT_QS + r * 132 + d0];
                af[mf][1] = smu[AT_QS + (r + 8) * 132 + d0];
                af[mf][2] = smu[AT_QS + r * 132 + d0 + 4];
                af[mf][3] = smu[AT_QS + (r + 8) * 132 + d0 + 4];
            }
            #pragma unroll
            for (int nb = 0; nb < 8; nb++) {
                uint32_t bf[2];
                bf[0] = smu[AT_K + (8 * nb + g) * 132 + d0];
                bf[1] = smu[AT_K + (8 * nb + g) * 132 + d0 + 4];
                mma_tf32(sacc[0][nb], af[0], bf);
                mma_tf32(sacc[1][nb], af[1], bf);
            }
        }

        // ---- causal mask (diagonal tile only) ----
        if (kt == qt) {
            #pragma unroll
            for (int mf = 0; mf < 2; mf++) {
                const int rl = 32 * w + 16 * mf + g;
                #pragma unroll
                for (int nb = 0; nb < 8; nb++)
                    #pragma unroll
                    for (int j = 0; j < 2; j++) {
                        const int col = 8 * nb + 2 * tid + j;
                        if (col > rl)     sacc[mf][nb][j]     = -1e30f;
                        if (col > rl + 8) sacc[mf][nb][2 + j] = -1e30f;
                    }
            }
        }

        // ---- online softmax (4 row-positions per thread; quad-local) ----
        #pragma unroll
        for (int mf = 0; mf < 2; mf++)
            #pragma unroll
            for (int hh = 0; hh < 2; hh++) {
                float mt = -1e30f;
                #pragma unroll
                for (int nb = 0; nb < 8; nb++)
                    mt = fmaxf(mt, fmaxf(sacc[mf][nb][2 * hh], sacc[mf][nb][2 * hh + 1]));
                mt = fmaxf(mt, __shfl_xor_sync(0xffffffffu, mt, 1));
                mt = fmaxf(mt, __shfl_xor_sync(0xffffffffu, mt, 2));

                const float mn = fmaxf(m_run[mf][hh], mt);
                const float sc = __expf(m_run[mf][hh] - mn);
                float ls = 0.f;
                const int rl = 32 * w + 16 * mf + g + 8 * hh;
                #pragma unroll
                for (int nb = 0; nb < 8; nb++) {
                    float p0 = __expf(sacc[mf][nb][2 * hh]     - mn);
                    float p1 = __expf(sacc[mf][nb][2 * hh + 1] - mn);
                    ls += p0 + p1;
                    uint2 u; u.x = f2tf(p0); u.y = f2tf(p1);
                    *(uint2*)(smu + AT_PS + rl * 68 + 8 * nb + 2 * tid) = u;
                }
                ls += __shfl_xor_sync(0xffffffffu, ls, 1);
                ls += __shfl_xor_sync(0xffffffffu, ls, 2);
                l_run[mf][hh] = l_run[mf][hh] * sc + ls;
                m_run[mf][hh] = mn;
                #pragma unroll
                for (int nb = 0; nb < 16; nb++) {
                    oacc[mf][nb][2 * hh]     *= sc;
                    oacc[mf][nb][2 * hh + 1] *= sc;
                }
            }
        __syncwarp();

        // ---- O += P @ Ktile : 8 k-steps over keys; 16 d-blocks; 2 m-frags ----
        #pragma unroll
        for (int ks = 0; ks < 8; ks++) {
            const int s0 = 8 * ks + tid;
            uint32_t af[2][4];
            #pragma unroll
            for (int mf = 0; mf < 2; mf++) {
                const int r = 32 * w + 16 * mf + g;
                af[mf][0] = smu[AT_PS + r * 68 + s0];
                af[mf][1] = smu[AT_PS + (r + 8) * 68 + s0];
                af[mf][2] = smu[AT_PS + r * 68 + s0 + 4];
                af[mf][3] = smu[AT_PS + (r + 8) * 68 + s0 + 4];
            }
            #pragma unroll
            for (int nb = 0; nb < 16; nb++) {
                uint32_t bf[2];
                bf[0] = smu[AT_K + s0 * 132 + 8 * nb + g];
                bf[1] = smu[AT_K + (s0 + 4) * 132 + 8 * nb + g];
                mma_tf32(oacc[0][nb], af[0], bf);
                mma_tf32(oacc[1][nb], af[1], bf);
            }
        }
    }

    // ---- epilogue: ctx = O / l ----
    #pragma unroll
    for (int mf = 0; mf < 2; mf++)
        #pragma unroll
        for (int hh = 0; hh < 2; hh++) {
            const int rl = 32 * w + 16 * mf + g + 8 * hh;
            const float inv = 1.f / l_run[mf][hh];
            float* dst = ctx + qbase + (long)rl * 128;
            #pragma unroll
            for (int nb = 0; nb < 16; nb++)
                *(float2*)(dst + 8 * nb + 2 * tid) =
                    make_float2(oacc[mf][nb][2 * hh] * inv, oacc[mf][nb][2 * hh + 1] * inv);
        }
}

// ===========================================================================
extern "C" void kernel_launch(void* const* d_in, const int* in_sizes, int n_in,
                              void* d_out, int out_size)
{
    const float* x     = (const float*)d_in[0];
    const float* W_dq  = (const float*)d_in[1];
    const float* W_uq  = (const float*)d_in[2];
    const float* W_dkv = (const float*)d_in[3];
    const float* W_uk  = (const float*)d_in[4];
    const float* W_uv  = (const float*)d_in[5];
    const float* W_o   = (const float*)d_in[6];

    float* y   = (float*)d_out;
    float* ckv = y + (long)BT * Cc;

    float *P, *M, *Nt, *R, *Aq, *QLp, *CT;
    cudaGetSymbolAddress((void**)&P,  g_P);
    cudaGetSymbolAddress((void**)&M,  g_M);
    cudaGetSymbolAddress((void**)&Nt, g_Nt);
    cudaGetSymbolAddress((void**)&R,  g_R);
    cudaGetSymbolAddress((void**)&Aq, g_Aq);
    cudaGetSymbolAddress((void**)&QLp, g_ql);
    cudaGetSymbolAddress((void**)&CT, g_ct);

    const int NONE = 1 << 30;
    const size_t S64   = (128 * 20 + 64 * 20) * 4;
    const size_t S128  = (128 * 20 + 128 * 20) * 4;
    const size_t S64C  = 2 * S64;

    // Exact fp32 precompute chain: P -> M -> Nt
    pk_kernel<<<128, 128>>>(W_uq, W_uk, P);
    m_kernel<<<1024, 128>>>(W_dq, P, M);
    n_kernel<<<dim3(128, 16), 128>>>(W_uq, M, Nt);

    // Fused: Aq = x @ W_dq^T  |  ckv = x @ W_dkv^T   (compensated tf32 ~ fp32)
    tgemm<64, false, true><<<dim3(32, 4), 256, S64C>>>(
        x, W_dq, Aq, W_dkv, ckv, 1024, 1024, 1024, 128, 0, 0, 0, 2);

    // ql[h] = Aq @ N[h]   (batched 16, K=128)
    tgemm<128, false, false><<<dim3(32, 1, 16), 256, S128>>>(
        Aq, Nt, QLp, nullptr, nullptr, 128, 128, 128, 128,
        0, 128 * 128, (long)BT * 128, NONE);

    // R = W_o @ W_uv   (1024 x 128, K=1024, NN)
    tgemm<64, true, false><<<dim3(8, 2), 256, S64>>>(
        W_o, W_uv, R, nullptr, nullptr, 1024, 1024, 128, 128, 0, 0, 0, NONE);

    // flash attention -> ctx
    cudaFuncSetAttribute(attn2_kernel, cudaFuncAttributeMaxDynamicSharedMemorySize,
                         AT_WORDS * 4);
    attn2_kernel<<<dim3(32, 32, 1), 64, AT_WORDS * 4>>>(QLp, ckv, CT);

    // y[:, h*64:] = ctx[h] @ R[h*64:, :]^T   (batched 16, K=128, N=64)
    tgemm<64, false, false><<<dim3(32, 1, 16), 256, S64>>>(
        CT, R, y, nullptr, nullptr, 128, 128, 128, 1024,
        (long)BT * 128, 64 * 128, 64, NONE);
}

// round 6
// speedup vs baseline: 1.3508x; 1.3508x over previous
#include <cuda_runtime.h>
#include <cstdint>

// Problem constants (fixed by setup_inputs)
#define Bb    2
#define Tt    2048
#define Cc    1024
#define QLd   128
#define KVL   128
#define NHh   16
#define HSd   64
#define BT    (Bb*Tt)          // 4096

// Scratch (device globals: no allocation allowed)
__device__ float g_P [QLd*KVL];          // W_uq^T @ W_uk          (128,128)
__device__ float g_M [Cc*KVL];           // W_dq^T @ P             (1024,128)
__device__ float g_Nt[NHh*KVL*QLd];      // Nt[h][j][i] = N[h][i][j]
__device__ float g_R [Cc*KVL];           // W_o @ W_uv             (1024,128)
__device__ float g_Aq[BT*QLd];           // x @ W_dq^T             (4096,128)
__device__ float g_ql[NHh*BT*KVL];       // latent queries         (16,4096,128)
__device__ float g_ct[NHh*BT*KVL];       // latent context         (16,4096,128)

__device__ __forceinline__ uint32_t f2tf(float f) {
    uint32_t u;
    asm("cvt.rna.tf32.f32 %0, %1;" : "=r"(u) : "f"(f));
    return u;
}
__device__ __forceinline__ void mma_tf32(float* d, const uint32_t* a, const uint32_t* b) {
    asm volatile(
        "mma.sync.aligned.m16n8k8.row.col.f32.tf32.tf32.f32 "
        "{%0,%1,%2,%3}, {%4,%5,%6,%7}, {%8,%9}, {%0,%1,%2,%3};"
        : "+f"(d[0]), "+f"(d[1]), "+f"(d[2]), "+f"(d[3])
        : "r"(a[0]), "r"(a[1]), "r"(a[2]), "r"(a[3]), "r"(b[0]), "r"(b[1]));
}

// ===========================================================================
// tf32 tensor-core GEMM (unchanged from R4/R5)
// ===========================================================================
template<int BN, bool NN, bool COMP>
__global__ __launch_bounds__(256)
void tgemm(const float* __restrict__ A, const float* __restrict__ B,
           float* __restrict__ C, const float* __restrict__ B2,
           float* __restrict__ C2, int K,
           int lda, int ldb, int ldc, long sA, long sB, long sC, int nb1)
{
    constexpr int BM = 128, AW = BM * 20, BW = BN * 20;
    constexpr int NF = BN / 16;
    extern __shared__ uint32_t sh[];
    uint32_t* Ah = sh;
    uint32_t* Bh = sh + AW;
    uint32_t* Al = sh + AW + BW;
    uint32_t* Bl = sh + 2 * AW + BW;

    const int z = blockIdx.z;
    A += (long)z * sA;
    const float* Bp = B;  float* Cp = C;
    int by = blockIdx.y;
    if (by >= nb1) { Bp = B2; Cp = C2; by -= nb1; }
    Bp += (long)z * sB;  Cp += (long)z * sC;

    const int m0 = blockIdx.x * BM, n0 = by * BN;
    const int t = threadIdx.x;
    const int wid = t >> 5, g = (t & 31) >> 2, tid = t & 3;
    const int wm = wid >> 1, wn = wid & 1;

    float acc[2][NF][4];
    #pragma unroll
    for (int i = 0; i < 2; i++)
        #pragma unroll
        for (int j = 0; j < NF; j++)
            #pragma unroll
            for (int q = 0; q < 4; q++) acc[i][j][q] = 0.f;

    for (int k0 = 0; k0 < K; k0 += 16) {
        #pragma unroll
        for (int i = 0; i < 2; i++) {
            int idx = t + i * 256;
            int r = idx >> 2, cg = (idx & 3) * 4;
            float4 v = *(const float4*)(A + (long)(m0 + r) * lda + k0 + cg);
            uint4 h; h.x = f2tf(v.x); h.y = f2tf(v.y); h.z = f2tf(v.z); h.w = f2tf(v.w);
            *(uint4*)(Ah + r * 20 + cg) = h;
            if (COMP) {
                uint4 l;
                l.x = f2tf(v.x - __uint_as_float(h.x));
                l.y = f2tf(v.y - __uint_as_float(h.y));
                l.z = f2tf(v.z - __uint_as_float(h.z));
                l.w = f2tf(v.w - __uint_as_float(h.w));
                *(uint4*)(Al + r * 20 + cg) = l;
            }
        }
        if (!NN) {
            #pragma unroll
            for (int i = 0; i < BN / 64; i++) {
                int idx = t + i * 256;
                int r = idx >> 2, cg = (idx & 3) * 4;
                float4 v = *(const float4*)(Bp + (long)(n0 + r) * ldb + k0 + cg);
                uint4 h; h.x = f2tf(v.x); h.y = f2tf(v.y); h.z = f2tf(v.z); h.w = f2tf(v.w);
                *(uint4*)(Bh + r * 20 + cg) = h;
                if (COMP) {
                    uint4 l;
                    l.x = f2tf(v.x - __uint_as_float(h.x));
                    l.y = f2tf(v.y - __uint_as_float(h.y));
                    l.z = f2tf(v.z - __uint_as_float(h.z));
                    l.w = f2tf(v.w - __uint_as_float(h.w));
                    *(uint4*)(Bl + r * 20 + cg) = l;
                }
            }
        } else {
            #pragma unroll
            for (int i = 0; i < BN / 64; i++) {
                int idx = t + i * 256;
                int kr = idx >> (BN == 64 ? 4 : 5);
                int nn = (idx & (BN / 4 - 1)) * 4;
                float4 v = *(const float4*)(Bp + (long)(k0 + kr) * ldb + n0 + nn);
                Bh[(nn + 0) * 20 + kr] = f2tf(v.x);
                Bh[(nn + 1) * 20 + kr] = f2tf(v.y);
                Bh[(nn + 2) * 20 + kr] = f2tf(v.z);
                Bh[(nn + 3) * 20 + kr] = f2tf(v.w);
            }
        }
        __syncthreads();

        #pragma unroll
        for (int s = 0; s < 2; s++) {
            const int kk = 8 * s + tid;
            uint32_t ah[2][4], al[2][4];
            #pragma unroll
            for (int mf = 0; mf < 2; mf++) {
                int r = wm * 32 + 16 * mf + g;
                ah[mf][0] = Ah[r * 20 + kk];       ah[mf][1] = Ah[(r + 8) * 20 + kk];
                ah[mf][2] = Ah[r * 20 + kk + 4];   ah[mf][3] = Ah[(r + 8) * 20 + kk + 4];
                if (COMP) {
                    al[mf][0] = Al[r * 20 + kk];     al[mf][1] = Al[(r + 8) * 20 + kk];
                    al[mf][2] = Al[r * 20 + kk + 4]; al[mf][3] = Al[(r + 8) * 20 + kk + 4];
                }
            }
            uint32_t bh[NF][2], bl[NF][2];
            #pragma unroll
            for (int nf = 0; nf < NF; nf++) {
                int n = wn * (BN / 2) + 8 * nf + g;
                bh[nf][0] = Bh[n * 20 + kk];  bh[nf][1] = Bh[n * 20 + kk + 4];
                if (COMP) { bl[nf][0] = Bl[n * 20 + kk]; bl[nf][1] = Bl[n * 20 + kk + 4]; }
            }
            #pragma unroll
            for (int mf = 0; mf < 2; mf++)
                #pragma unroll
                for (int nf = 0; nf < NF; nf++) {
                    mma_tf32(acc[mf][nf], ah[mf], bh[nf]);
                    if (COMP) {
                        mma_tf32(acc[mf][nf], ah[mf], bl[nf]);
                        mma_tf32(acc[mf][nf], al[mf], bh[nf]);
                    }
                }
        }
        __syncthreads();
    }

    #pragma unroll
    for (int mf = 0; mf < 2; mf++) {
        const int r0 = m0 + wm * 32 + 16 * mf + g;
        #pragma unroll
        for (int nf = 0; nf < NF; nf++) {
            const int c = n0 + wn * (BN / 2) + 8 * nf + 2 * tid;
            *(float2*)(Cp + (long)r0 * ldc + c)       = make_float2(acc[mf][nf][0], acc[mf][nf][1]);
            *(float2*)(Cp + (long)(r0 + 8) * ldc + c) = make_float2(acc[mf][nf][2], acc[mf][nf][3]);
        }
    }
}

// ===========================================================================
// Tiny fp32-exact precompute kernels (unchanged from R5)
// ===========================================================================
__global__ __launch_bounds__(128)
void pk_kernel(const float* __restrict__ W_uq, const float* __restrict__ W_uk,
               float* __restrict__ P)
{
    const int i = blockIdx.x, j = threadIdx.x;
    float s = 0.f;
    #pragma unroll 8
    for (int c = 0; c < 1024; c++)
        s += W_uq[c * 128 + i] * W_uk[c * 128 + j];
    P[i * 128 + j] = s;
}
__global__ __launch_bounds__(128)
void m_kernel(const float* __restrict__ W_dq, const float* __restrict__ P,
              float* __restrict__ M)
{
    const int c = blockIdx.x, j = threadIdx.x;
    float s = 0.f;
    #pragma unroll 8
    for (int i = 0; i < 128; i++)
        s += W_dq[i * 1024 + c] * P[i * 128 + j];
    M[c * 128 + j] = s;
}
__global__ __launch_bounds__(128)
void n_kernel(const float* __restrict__ W_uq, const float* __restrict__ M,
              float* __restrict__ Nt)
{
    const int j = blockIdx.x, h = blockIdx.y, i = threadIdx.x;
    float s = 0.f;
    #pragma unroll 8
    for (int d = 0; d < 64; d++)
        s += W_uq[(h * 64 + d) * 128 + i] * M[(h * 64 + d) * 128 + j];
    Nt[(h * 128 + j) * 128 + i] = s;
}

// ===========================================================================
// mma.sync tf32 flash attention v3.
// CTA: 64 queries, 4 warps x 16 rows (R4's proven per-warp shape, no spills).
// Single K copy, 85 KB smem -> 2 CTAs/SM: two independently-synced CTAs
// overlap K-load/softmax phases with each other's MMA phases.
// Grid (h fastest) so 16 heads stream the same K tiles -> L2 reuse.
// ===========================================================================
#define AT_QS 0              // 64 x 132
#define AT_K  8448           // 64 x 132
#define AT_PS 16896          // 64 x 68
#define AT_WORDS 21248       // 84992 bytes

__global__ __launch_bounds__(128, 2)
void attn3_kernel(const float* __restrict__ ql, const float* __restrict__ ckv,
                  float* __restrict__ ctx)
{
    extern __shared__ uint32_t smu[];
    const int t = threadIdx.x;
    const int w = t >> 5, lid = t & 31;
    const int g = lid >> 2, tid = lid & 3;

    const int h  = blockIdx.x;               // 0..15 (fastest: K-tile L2 sharing)
    const int qt = 31 - blockIdx.y;          // heavy tiles first
    const int b  = blockIdx.z;
    const long qbase = ((long)h * BT + (long)b * Tt + (long)qt * 64) * 128;
    const long kbase = (long)b * Tt * 128;

    // Q tile: 64x128, prescaled by 1/8, tf32
    {
        const float* qs = ql + qbase;
        #pragma unroll
        for (int i = 0; i < 16; i++) {
            int idx = t + i * 128;
            int r = idx >> 5, c = (idx & 31) * 4;
            float4 v = *(const float4*)(qs + (long)r * 128 + c);
            uint4 u;
            u.x = f2tf(v.x * 0.125f); u.y = f2tf(v.y * 0.125f);
            u.z = f2tf(v.z * 0.125f); u.w = f2tf(v.w * 0.125f);
            *(uint4*)(smu + AT_QS + r * 132 + c) = u;
        }
    }

    float oacc[16][4];
    #pragma unroll
    for (int nb = 0; nb < 16; nb++)
        #pragma unroll
        for (int q = 0; q < 4; q++) oacc[nb][q] = 0.f;

    float m_run[2] = { -1e30f, -1e30f };
    float l_run[2] = { 0.f, 0.f };

    const int rl0 = 16 * w + g;              // local query row (0..63)

    for (int kt = 0; kt <= qt; kt++) {
        __syncthreads();     // prev PV reads of K done; also fences Q stores on iter 0
        {
            const float* ks = ckv + kbase + (long)kt * 64 * 128;
            #pragma unroll
            for (int i = 0; i < 16; i++) {
                int idx = t + i * 128;
                int r = idx >> 5, c = (idx & 31) * 4;
                float4 v = *(const float4*)(ks + (long)r * 128 + c);
                uint4 u;
                u.x = f2tf(v.x); u.y = f2tf(v.y); u.z = f2tf(v.z); u.w = f2tf(v.w);
                *(uint4*)(smu + AT_K + r * 132 + c) = u;
            }
        }
        __syncthreads();

        // ---- S = Q K^T : 16 k-steps over d; 8 key-blocks ----
        float sacc[8][4];
        #pragma unroll
        for (int nb = 0; nb < 8; nb++)
            #pragma unroll
            for (int q = 0; q < 4; q++) sacc[nb][q] = 0.f;

        #pragma unroll
        for (int ks = 0; ks < 16; ks++) {
            const int d0 = 8 * ks + tid;
            uint32_t af[4];
            af[0] = smu[AT_QS + rl0 * 132 + d0];
            af[1] = smu[AT_QS + (rl0 + 8) * 132 + d0];
            af[2] = smu[AT_QS + rl0 * 132 + d0 + 4];
            af[3] = smu[AT_QS + (rl0 + 8) * 132 + d0 + 4];
            #pragma unroll
            for (int nb = 0; nb < 8; nb++) {
                uint32_t bf[2];
                bf[0] = smu[AT_K + (8 * nb + g) * 132 + d0];
                bf[1] = smu[AT_K + (8 * nb + g) * 132 + d0 + 4];
                mma_tf32(sacc[nb], af, bf);
            }
        }

        // ---- causal mask (diagonal tile only; rows/cols local to 64) ----
        if (kt == qt) {
            #pragma unroll
            for (int nb = 0; nb < 8; nb++)
                #pragma unroll
                for (int j = 0; j < 2; j++) {
                    const int col = 8 * nb + 2 * tid + j;
                    if (col > rl0)     sacc[nb][j]     = -1e30f;
                    if (col > rl0 + 8) sacc[nb][2 + j] = -1e30f;
                }
        }

        // ---- online softmax (rows rl0, rl0+8; quad-local reductions) ----
        #pragma unroll
        for (int hh = 0; hh < 2; hh++) {
            float mt = -1e30f;
            #pragma unroll
            for (int nb = 0; nb < 8; nb++)
                mt = fmaxf(mt, fmaxf(sacc[nb][2 * hh], sacc[nb][2 * hh + 1]));
            mt = fmaxf(mt, __shfl_xor_sync(0xffffffffu, mt, 1));
            mt = fmaxf(mt, __shfl_xor_sync(0xffffffffu, mt, 2));

            const float mn = fmaxf(m_run[hh], mt);
            const float sc = __expf(m_run[hh] - mn);
            float ls = 0.f;
            const int rl = rl0 + 8 * hh;
            #pragma unroll
            for (int nb = 0; nb < 8; nb++) {
                float p0 = __expf(sacc[nb][2 * hh]     - mn);
                float p1 = __expf(sacc[nb][2 * hh + 1] - mn);
                ls += p0 + p1;
                uint2 u; u.x = f2tf(p0); u.y = f2tf(p1);
                *(uint2*)(smu + AT_PS + rl * 68 + 8 * nb + 2 * tid) = u;
            }
            ls += __shfl_xor_sync(0xffffffffu, ls, 1);
            ls += __shfl_xor_sync(0xffffffffu, ls, 2);
            l_run[hh] = l_run[hh] * sc + ls;
            m_run[hh] = mn;
            #pragma unroll
            for (int nb = 0; nb < 16; nb++) {
                oacc[nb][2 * hh]     *= sc;
                oacc[nb][2 * hh + 1] *= sc;
            }
        }
        __syncwarp();   // P rows are warp-private: warp sync suffices

        // ---- O += P @ Ktile : 8 k-steps over keys; 16 d-blocks ----
        #pragma unroll
        for (int ks = 0; ks < 8; ks++) {
            const int s0 = 8 * ks + tid;
            uint32_t af[4];
            af[0] = smu[AT_PS + rl0 * 68 + s0];
            af[1] = smu[AT_PS + (rl0 + 8) * 68 + s0];
            af[2] = smu[AT_PS + rl0 * 68 + s0 + 4];
            af[3] = smu[AT_PS + (rl0 + 8) * 68 + s0 + 4];
            #pragma unroll
            for (int nb = 0; nb < 16; nb++) {
                uint32_t bf[2];
                bf[0] = smu[AT_K + s0 * 132 + 8 * nb + g];
                bf[1] = smu[AT_K + (s0 + 4) * 132 + 8 * nb + g];
                mma_tf32(oacc[nb], af, bf);
            }
        }
    }

    // ---- epilogue: ctx = O / l ----
    #pragma unroll
    for (int hh = 0; hh < 2; hh++) {
        const int rl = rl0 + 8 * hh;
        const float inv = 1.f / l_run[hh];
        float* dst = ctx + qbase + (long)rl * 128;
        #pragma unroll
        for (int nb = 0; nb < 16; nb++)
            *(float2*)(dst + 8 * nb + 2 * tid) =
                make_float2(oacc[nb][2 * hh] * inv, oacc[nb][2 * hh + 1] * inv);
    }
}

// ===========================================================================
extern "C" void kernel_launch(void* const* d_in, const int* in_sizes, int n_in,
                              void* d_out, int out_size)
{
    const float* x     = (const float*)d_in[0];
    const float* W_dq  = (const float*)d_in[1];
    const float* W_uq  = (const float*)d_in[2];
    const float* W_dkv = (const float*)d_in[3];
    const float* W_uk  = (const float*)d_in[4];
    const float* W_uv  = (const float*)d_in[5];
    const float* W_o   = (const float*)d_in[6];

    float* y   = (float*)d_out;
    float* ckv = y + (long)BT * Cc;

    float *P, *M, *Nt, *R, *Aq, *QLp, *CT;
    cudaGetSymbolAddress((void**)&P,  g_P);
    cudaGetSymbolAddress((void**)&M,  g_M);
    cudaGetSymbolAddress((void**)&Nt, g_Nt);
    cudaGetSymbolAddress((void**)&R,  g_R);
    cudaGetSymbolAddress((void**)&Aq, g_Aq);
    cudaGetSymbolAddress((void**)&QLp, g_ql);
    cudaGetSymbolAddress((void**)&CT, g_ct);

    const int NONE = 1 << 30;
    const size_t S64   = (128 * 20 + 64 * 20) * 4;
    const size_t S128  = (128 * 20 + 128 * 20) * 4;
    const size_t S64C  = 2 * S64;

    // Exact fp32 precompute chain: P -> M -> Nt
    pk_kernel<<<128, 128>>>(W_uq, W_uk, P);
    m_kernel<<<1024, 128>>>(W_dq, P, M);
    n_kernel<<<dim3(128, 16), 128>>>(W_uq, M, Nt);

    // Fused: Aq = x @ W_dq^T  |  ckv = x @ W_dkv^T   (compensated tf32 ~ fp32)
    tgemm<64, false, true><<<dim3(32, 4), 256, S64C>>>(
        x, W_dq, Aq, W_dkv, ckv, 1024, 1024, 1024, 128, 0, 0, 0, 2);

    // ql[h] = Aq @ N[h]   (batched 16, K=128)
    tgemm<128, false, false><<<dim3(32, 1, 16), 256, S128>>>(
        Aq, Nt, QLp, nullptr, nullptr, 128, 128, 128, 128,
        0, 128 * 128, (long)BT * 128, NONE);

    // R = W_o @ W_uv   (1024 x 128, K=1024, NN)
    tgemm<64, true, false><<<dim3(8, 2), 256, S64>>>(
        W_o, W_uv, R, nullptr, nullptr, 1024, 1024, 128, 128, 0, 0, 0, NONE);

    // flash attention -> ctx   (grid: h fastest for K-tile L2 sharing)
    cudaFuncSetAttribute(attn3_kernel, cudaFuncAttributeMaxDynamicSharedMemorySize,
                         AT_WORDS * 4);
    attn3_kernel<<<dim3(16, 32, 2), 128, AT_WORDS * 4>>>(QLp, ckv, CT);

    // y[:, h*64:] = ctx[h] @ R[h*64:, :]^T   (batched 16, K=128, N=64)
    tgemm<64, false, false><<<dim3(32, 1, 16), 256, S64>>>(
        CT, R, y, nullptr, nullptr, 128, 128, 128, 1024,
        (long)BT * 128, 64 * 128, 64, NONE);
}

// round 7
// speedup vs baseline: 1.4637x; 1.0836x over previous
#include <cuda_runtime.h>
#include <cstdint>

// Problem constants (fixed by setup_inputs)
#define Bb    2
#define Tt    2048
#define Cc    1024
#define QLd   128
#define KVL   128
#define NHh   16
#define HSd   64
#define BT    (Bb*Tt)          // 4096

// Scratch (device globals: no allocation allowed)
__device__ float g_P [QLd*KVL];          // W_uq^T @ W_uk          (128,128)
__device__ float g_M [Cc*KVL];           // W_dq^T @ P             (1024,128)
__device__ float g_Nt[NHh*KVL*QLd];      // Nt[h][j][i] = N[h][i][j]
__device__ float g_R [Cc*KVL];           // W_o @ W_uv             (1024,128)
__device__ float g_Aq[BT*QLd];           // x @ W_dq^T             (4096,128)
__device__ float g_ql[NHh*BT*KVL];       // latent queries         (16,4096,128)
__device__ float g_ct[NHh*BT*KVL];       // latent context         (16,4096,128)

__device__ __forceinline__ uint32_t f2tf(float f) {
    uint32_t u;
    asm("cvt.rna.tf32.f32 %0, %1;" : "=r"(u) : "f"(f));
    return u;
}
__device__ __forceinline__ void mma_tf32(float* d, const uint32_t* a, const uint32_t* b) {
    asm volatile(
        "mma.sync.aligned.m16n8k8.row.col.f32.tf32.tf32.f32 "
        "{%0,%1,%2,%3}, {%4,%5,%6,%7}, {%8,%9}, {%0,%1,%2,%3};"
        : "+f"(d[0]), "+f"(d[1]), "+f"(d[2]), "+f"(d[3])
        : "r"(a[0]), "r"(a[1]), "r"(a[2]), "r"(a[3]), "r"(b[0]), "r"(b[1]));
}

// ===========================================================================
// tf32 tensor-core GEMM (unchanged from R4-R6)
// ===========================================================================
template<int BN, bool NN, bool COMP>
__global__ __launch_bounds__(256)
void tgemm(const float* __restrict__ A, const float* __restrict__ B,
           float* __restrict__ C, const float* __restrict__ B2,
           float* __restrict__ C2, int K,
           int lda, int ldb, int ldc, long sA, long sB, long sC, int nb1)
{
    constexpr int BM = 128, AW = BM * 20, BW = BN * 20;
    constexpr int NF = BN / 16;
    extern __shared__ uint32_t sh[];
    uint32_t* Ah = sh;
    uint32_t* Bh = sh + AW;
    uint32_t* Al = sh + AW + BW;
    uint32_t* Bl = sh + 2 * AW + BW;

    const int z = blockIdx.z;
    A += (long)z * sA;
    const float* Bp = B;  float* Cp = C;
    int by = blockIdx.y;
    if (by >= nb1) { Bp = B2; Cp = C2; by -= nb1; }
    Bp += (long)z * sB;  Cp += (long)z * sC;

    const int m0 = blockIdx.x * BM, n0 = by * BN;
    const int t = threadIdx.x;
    const int wid = t >> 5, g = (t & 31) >> 2, tid = t & 3;
    const int wm = wid >> 1, wn = wid & 1;

    float acc[2][NF][4];
    #pragma unroll
    for (int i = 0; i < 2; i++)
        #pragma unroll
        for (int j = 0; j < NF; j++)
            #pragma unroll
            for (int q = 0; q < 4; q++) acc[i][j][q] = 0.f;

    for (int k0 = 0; k0 < K; k0 += 16) {
        #pragma unroll
        for (int i = 0; i < 2; i++) {
            int idx = t + i * 256;
            int r = idx >> 2, cg = (idx & 3) * 4;
            float4 v = *(const float4*)(A + (long)(m0 + r) * lda + k0 + cg);
            uint4 h; h.x = f2tf(v.x); h.y = f2tf(v.y); h.z = f2tf(v.z); h.w = f2tf(v.w);
            *(uint4*)(Ah + r * 20 + cg) = h;
            if (COMP) {
                uint4 l;
                l.x = f2tf(v.x - __uint_as_float(h.x));
                l.y = f2tf(v.y - __uint_as_float(h.y));
                l.z = f2tf(v.z - __uint_as_float(h.z));
                l.w = f2tf(v.w - __uint_as_float(h.w));
                *(uint4*)(Al + r * 20 + cg) = l;
            }
        }
        if (!NN) {
            #pragma unroll
            for (int i = 0; i < BN / 64; i++) {
                int idx = t + i * 256;
                int r = idx >> 2, cg = (idx & 3) * 4;
                float4 v = *(const float4*)(Bp + (long)(n0 + r) * ldb + k0 + cg);
                uint4 h; h.x = f2tf(v.x); h.y = f2tf(v.y); h.z = f2tf(v.z); h.w = f2tf(v.w);
                *(uint4*)(Bh + r * 20 + cg) = h;
                if (COMP) {
                    uint4 l;
                    l.x = f2tf(v.x - __uint_as_float(h.x));
                    l.y = f2tf(v.y - __uint_as_float(h.y));
                    l.z = f2tf(v.z - __uint_as_float(h.z));
                    l.w = f2tf(v.w - __uint_as_float(h.w));
                    *(uint4*)(Bl + r * 20 + cg) = l;
                }
            }
        } else {
            #pragma unroll
            for (int i = 0; i < BN / 64; i++) {
                int idx = t + i * 256;
                int kr = idx >> (BN == 64 ? 4 : 5);
                int nn = (idx & (BN / 4 - 1)) * 4;
                float4 v = *(const float4*)(Bp + (long)(k0 + kr) * ldb + n0 + nn);
                Bh[(nn + 0) * 20 + kr] = f2tf(v.x);
                Bh[(nn + 1) * 20 + kr] = f2tf(v.y);
                Bh[(nn + 2) * 20 + kr] = f2tf(v.z);
                Bh[(nn + 3) * 20 + kr] = f2tf(v.w);
            }
        }
        __syncthreads();

        #pragma unroll
        for (int s = 0; s < 2; s++) {
            const int kk = 8 * s + tid;
            uint32_t ah[2][4], al[2][4];
            #pragma unroll
            for (int mf = 0; mf < 2; mf++) {
                int r = wm * 32 + 16 * mf + g;
                ah[mf][0] = Ah[r * 20 + kk];       ah[mf][1] = Ah[(r + 8) * 20 + kk];
                ah[mf][2] = Ah[r * 20 + kk + 4];   ah[mf][3] = Ah[(r + 8) * 20 + kk + 4];
                if (COMP) {
                    al[mf][0] = Al[r * 20 + kk];     al[mf][1] = Al[(r + 8) * 20 + kk];
                    al[mf][2] = Al[r * 20 + kk + 4]; al[mf][3] = Al[(r + 8) * 20 + kk + 4];
                }
            }
            uint32_t bh[NF][2], bl[NF][2];
            #pragma unroll
            for (int nf = 0; nf < NF; nf++) {
                int n = wn * (BN / 2) + 8 * nf + g;
                bh[nf][0] = Bh[n * 20 + kk];  bh[nf][1] = Bh[n * 20 + kk + 4];
                if (COMP) { bl[nf][0] = Bl[n * 20 + kk]; bl[nf][1] = Bl[n * 20 + kk + 4]; }
            }
            #pragma unroll
            for (int mf = 0; mf < 2; mf++)
                #pragma unroll
                for (int nf = 0; nf < NF; nf++) {
                    mma_tf32(acc[mf][nf], ah[mf], bh[nf]);
                    if (COMP) {
                        mma_tf32(acc[mf][nf], ah[mf], bl[nf]);
                        mma_tf32(acc[mf][nf], al[mf], bh[nf]);
                    }
                }
        }
        __syncthreads();
    }

    #pragma unroll
    for (int mf = 0; mf < 2; mf++) {
        const int r0 = m0 + wm * 32 + 16 * mf + g;
        #pragma unroll
        for (int nf = 0; nf < NF; nf++) {
            const int c = n0 + wn * (BN / 2) + 8 * nf + 2 * tid;
            *(float2*)(Cp + (long)r0 * ldc + c)       = make_float2(acc[mf][nf][0], acc[mf][nf][1]);
            *(float2*)(Cp + (long)(r0 + 8) * ldc + c) = make_float2(acc[mf][nf][2], acc[mf][nf][3]);
        }
    }
}

// ===========================================================================
// Tiny fp32-exact precompute kernels (unchanged)
// ===========================================================================
__global__ __launch_bounds__(128)
void pk_kernel(const float* __restrict__ W_uq, const float* __restrict__ W_uk,
               float* __restrict__ P)
{
    const int i = blockIdx.x, j = threadIdx.x;
    float s = 0.f;
    #pragma unroll 8
    for (int c = 0; c < 1024; c++)
        s += W_uq[c * 128 + i] * W_uk[c * 128 + j];
    P[i * 128 + j] = s;
}
__global__ __launch_bounds__(128)
void m_kernel(const float* __restrict__ W_dq, const float* __restrict__ P,
              float* __restrict__ M)
{
    const int c = blockIdx.x, j = threadIdx.x;
    float s = 0.f;
    #pragma unroll 8
    for (int i = 0; i < 128; i++)
        s += W_dq[i * 1024 + c] * P[i * 128 + j];
    M[c * 128 + j] = s;
}
__global__ __launch_bounds__(128)
void n_kernel(const float* __restrict__ W_uq, const float* __restrict__ M,
              float* __restrict__ Nt)
{
    const int j = blockIdx.x, h = blockIdx.y, i = threadIdx.x;
    float s = 0.f;
    #pragma unroll 8
    for (int d = 0; d < 64; d++)
        s += W_uq[(h * 64 + d) * 128 + i] * M[(h * 64 + d) * 128 + j];
    Nt[(h * 128 + j) * 128 + i] = s;
}

// ===========================================================================
// mma.sync tf32 flash attention v4.
// CTA: 64 queries, 4 warps x 16 rows, 2 CTAs/SM.
// Q A-fragments live in REGISTERS (no S-phase A-LDS, no Q smem).
// Two K copies: K1 stride 132 (S-phase B, conflict-free),
//               K2 stride 136 (PV B, banks = 8*tid+g -> conflict-free).
// Crossbar model: ~2900 cyc/CTA-ktile vs R6's ~3840.
// ===========================================================================
#define AT_K1 0                  // 64 x 132
#define AT_K2 8448               // 64 x 136
#define AT_PS 17152              // 64 x 68
#define AT_WORDS 21504           // 86016 bytes

__global__ __launch_bounds__(128, 2)
void attn4_kernel(const float* __restrict__ ql, const float* __restrict__ ckv,
                  float* __restrict__ ctx)
{
    extern __shared__ uint32_t smu[];
    const int t = threadIdx.x;
    const int w = t >> 5, lid = t & 31;
    const int g = lid >> 2, tid = lid & 3;

    const int h  = blockIdx.x;               // 0..15 (fastest: K-tile L2 sharing)
    const int qt = 31 - blockIdx.y;          // heavy tiles first
    const int b  = blockIdx.z;
    const long qbase = ((long)h * BT + (long)b * Tt + (long)qt * 64) * 128;
    const long kbase = (long)b * Tt * 128;

    const int rl0 = 16 * w + g;              // local query row (0..63)

    // ---- Q A-fragments -> registers (prescaled by 1/8, tf32) ----
    uint32_t qf[16][4];
    {
        const float* qr0 = ql + qbase + (long)rl0 * 128;
        const float* qr1 = qr0 + 8 * 128;
        #pragma unroll
        for (int ks = 0; ks < 16; ks++) {
            const int c0 = 8 * ks + tid;
            qf[ks][0] = f2tf(qr0[c0]     * 0.125f);
            qf[ks][1] = f2tf(qr1[c0]     * 0.125f);
            qf[ks][2] = f2tf(qr0[c0 + 4] * 0.125f);
            qf[ks][3] = f2tf(qr1[c0 + 4] * 0.125f);
        }
    }

    float oacc[16][4];
    #pragma unroll
    for (int nb = 0; nb < 16; nb++)
        #pragma unroll
        for (int q = 0; q < 4; q++) oacc[nb][q] = 0.f;

    float m_run[2] = { -1e30f, -1e30f };
    float l_run[2] = { 0.f, 0.f };

    for (int kt = 0; kt <= qt; kt++) {
        __syncthreads();     // prev PV reads of K1/K2 done before overwrite
        {
            const float* ks = ckv + kbase + (long)kt * 64 * 128;
            #pragma unroll
            for (int i = 0; i < 16; i++) {
                int idx = t + i * 128;
                int r = idx >> 5, c = (idx & 31) * 4;
                float4 v = *(const float4*)(ks + (long)r * 128 + c);
                uint4 u;
                u.x = f2tf(v.x); u.y = f2tf(v.y); u.z = f2tf(v.z); u.w = f2tf(v.w);
                *(uint4*)(smu + AT_K1 + r * 132 + c) = u;
                *(uint4*)(smu + AT_K2 + r * 136 + c) = u;
            }
        }
        __syncthreads();

        // ---- S = Q K^T : Q from registers; B from K1 ----
        float sacc[8][4];
        #pragma unroll
        for (int nb = 0; nb < 8; nb++)
            #pragma unroll
            for (int q = 0; q < 4; q++) sacc[nb][q] = 0.f;

        #pragma unroll
        for (int ks = 0; ks < 16; ks++) {
            const int d0 = 8 * ks + tid;
            #pragma unroll
            for (int nb = 0; nb < 8; nb++) {
                uint32_t bf[2];
                bf[0] = smu[AT_K1 + (8 * nb + g) * 132 + d0];
                bf[1] = smu[AT_K1 + (8 * nb + g) * 132 + d0 + 4];
                mma_tf32(sacc[nb], qf[ks], bf);
            }
        }

        // ---- causal mask (diagonal tile only) ----
        if (kt == qt) {
            #pragma unroll
            for (int nb = 0; nb < 8; nb++)
                #pragma unroll
                for (int j = 0; j < 2; j++) {
                    const int col = 8 * nb + 2 * tid + j;
                    if (col > rl0)     sacc[nb][j]     = -1e30f;
                    if (col > rl0 + 8) sacc[nb][2 + j] = -1e30f;
                }
        }

        // ---- online softmax (rows rl0, rl0+8; quad-local reductions) ----
        #pragma unroll
        for (int hh = 0; hh < 2; hh++) {
            float mt = -1e30f;
            #pragma unroll
            for (int nb = 0; nb < 8; nb++)
                mt = fmaxf(mt, fmaxf(sacc[nb][2 * hh], sacc[nb][2 * hh + 1]));
            mt = fmaxf(mt, __shfl_xor_sync(0xffffffffu, mt, 1));
            mt = fmaxf(mt, __shfl_xor_sync(0xffffffffu, mt, 2));

            const float mn = fmaxf(m_run[hh], mt);
            const float sc = __expf(m_run[hh] - mn);
            float ls = 0.f;
            const int rl = rl0 + 8 * hh;
            #pragma unroll
            for (int nb = 0; nb < 8; nb++) {
                float p0 = __expf(sacc[nb][2 * hh]     - mn);
                float p1 = __expf(sacc[nb][2 * hh + 1] - mn);
                ls += p0 + p1;
                uint2 u; u.x = f2tf(p0); u.y = f2tf(p1);
                *(uint2*)(smu + AT_PS + rl * 68 + 8 * nb + 2 * tid) = u;
            }
            ls += __shfl_xor_sync(0xffffffffu, ls, 1);
            ls += __shfl_xor_sync(0xffffffffu, ls, 2);
            l_run[hh] = l_run[hh] * sc + ls;
            m_run[hh] = mn;
            #pragma unroll
            for (int nb = 0; nb < 16; nb++) {
                oacc[nb][2 * hh]     *= sc;
                oacc[nb][2 * hh + 1] *= sc;
            }
        }
        __syncwarp();   // P rows are warp-private

        // ---- O += P @ Ktile : A from PS; B from K2 (conflict-free) ----
        #pragma unroll
        for (int ks = 0; ks < 8; ks++) {
            const int s0 = 8 * ks + tid;
            uint32_t af[4];
            af[0] = smu[AT_PS + rl0 * 68 + s0];
            af[1] = smu[AT_PS + (rl0 + 8) * 68 + s0];
            af[2] = smu[AT_PS + rl0 * 68 + s0 + 4];
            af[3] = smu[AT_PS + (rl0 + 8) * 68 + s0 + 4];
            #pragma unroll
            for (int nb = 0; nb < 16; nb++) {
                uint32_t bf[2];
                bf[0] = smu[AT_K2 + s0 * 136 + 8 * nb + g];
                bf[1] = smu[AT_K2 + (s0 + 4) * 136 + 8 * nb + g];
                mma_tf32(oacc[nb], af, bf);
            }
        }
    }

    // ---- epilogue: ctx = O / l ----
    #pragma unroll
    for (int hh = 0; hh < 2; hh++) {
        const int rl = rl0 + 8 * hh;
        const float inv = 1.f / l_run[hh];
        float* dst = ctx + qbase + (long)rl * 128;
        #pragma unroll
        for (int nb = 0; nb < 16; nb++)
            *(float2*)(dst + 8 * nb + 2 * tid) =
                make_float2(oacc[nb][2 * hh] * inv, oacc[nb][2 * hh + 1] * inv);
    }
}

// ===========================================================================
extern "C" void kernel_launch(void* const* d_in, const int* in_sizes, int n_in,
                              void* d_out, int out_size)
{
    const float* x     = (const float*)d_in[0];
    const float* W_dq  = (const float*)d_in[1];
    const float* W_uq  = (const float*)d_in[2];
    const float* W_dkv = (const float*)d_in[3];
    const float* W_uk  = (const float*)d_in[4];
    const float* W_uv  = (const float*)d_in[5];
    const float* W_o   = (const float*)d_in[6];

    float* y   = (float*)d_out;
    float* ckv = y + (long)BT * Cc;

    float *P, *M, *Nt, *R, *Aq, *QLp, *CT;
    cudaGetSymbolAddress((void**)&P,  g_P);
    cudaGetSymbolAddress((void**)&M,  g_M);
    cudaGetSymbolAddress((void**)&Nt, g_Nt);
    cudaGetSymbolAddress((void**)&R,  g_R);
    cudaGetSymbolAddress((void**)&Aq, g_Aq);
    cudaGetSymbolAddress((void**)&QLp, g_ql);
    cudaGetSymbolAddress((void**)&CT, g_ct);

    const int NONE = 1 << 30;
    const size_t S64   = (128 * 20 + 64 * 20) * 4;
    const size_t S128  = (128 * 20 + 128 * 20) * 4;
    const size_t S64C  = 2 * S64;

    // Exact fp32 precompute chain: P -> M -> Nt
    pk_kernel<<<128, 128>>>(W_uq, W_uk, P);
    m_kernel<<<1024, 128>>>(W_dq, P, M);
    n_kernel<<<dim3(128, 16), 128>>>(W_uq, M, Nt);

    // Fused: Aq = x @ W_dq^T  |  ckv = x @ W_dkv^T   (compensated tf32 ~ fp32)
    tgemm<64, false, true><<<dim3(32, 4), 256, S64C>>>(
        x, W_dq, Aq, W_dkv, ckv, 1024, 1024, 1024, 128, 0, 0, 0, 2);

    // ql[h] = Aq @ N[h]   (batched 16, K=128)
    tgemm<128, false, false><<<dim3(32, 1, 16), 256, S128>>>(
        Aq, Nt, QLp, nullptr, nullptr, 128, 128, 128, 128,
        0, 128 * 128, (long)BT * 128, NONE);

    // R = W_o @ W_uv   (1024 x 128, K=1024, NN)
    tgemm<64, true, false><<<dim3(8, 2), 256, S64>>>(
        W_o, W_uv, R, nullptr, nullptr, 1024, 1024, 128, 128, 0, 0, 0, NONE);

    // flash attention -> ctx   (grid: h fastest for K-tile L2 sharing)
    cudaFuncSetAttribute(attn4_kernel, cudaFuncAttributeMaxDynamicSharedMemorySize,
                         AT_WORDS * 4);
    attn4_kernel<<<dim3(16, 32, 2), 128, AT_WORDS * 4>>>(QLp, ckv, CT);

    // y[:, h*64:] = ctx[h] @ R[h*64:, :]^T   (batched 16, K=128, N=64)
    tgemm<64, false, false><<<dim3(32, 1, 16), 256, S64>>>(
        CT, R, y, nullptr, nullptr, 128, 128, 128, 1024,
        (long)BT * 128, 64 * 128, 64, NONE);
}

// round 8
// speedup vs baseline: 1.6577x; 1.1325x over previous
#include <cuda_runtime.h>
#include <cstdint>

// Problem constants (fixed by setup_inputs)
#define Bb    2
#define Tt    2048
#define Cc    1024
#define QLd   128
#define KVL   128
#define NHh   16
#define HSd   64
#define BT    (Bb*Tt)          // 4096

// Scratch (device globals: no allocation allowed)
__device__ float g_P [QLd*KVL];          // W_uq^T @ W_uk          (128,128)
__device__ float g_M [Cc*KVL];           // W_dq^T @ P             (1024,128)
__device__ float g_Nt[NHh*KVL*QLd];      // Nt[h][j][i] = N[h][i][j]
__device__ float g_R [Cc*KVL];           // W_o @ W_uv             (1024,128)
__device__ float g_Aq[BT*QLd];           // x @ W_dq^T             (4096,128)
__device__ float g_ql[NHh*BT*KVL];       // latent queries         (16,4096,128)
__device__ float g_ct[NHh*BT*KVL];       // latent context (also GEMM partial scratch)

__device__ __forceinline__ uint32_t f2tf(float f) {
    uint32_t u;
    asm("cvt.rna.tf32.f32 %0, %1;" : "=r"(u) : "f"(f));
    return u;
}
__device__ __forceinline__ void mma_tf32(float* d, const uint32_t* a, const uint32_t* b) {
    asm volatile(
        "mma.sync.aligned.m16n8k8.row.col.f32.tf32.tf32.f32 "
        "{%0,%1,%2,%3}, {%4,%5,%6,%7}, {%8,%9}, {%0,%1,%2,%3};"
        : "+f"(d[0]), "+f"(d[1]), "+f"(d[2]), "+f"(d[3])
        : "r"(a[0]), "r"(a[1]), "r"(a[2]), "r"(a[3]), "r"(b[0]), "r"(b[1]));
}

// ===========================================================================
// tf32 tensor-core GEMM, software-pipelined (double-buffered smem + register
// prefetch of next K-tile). Batch axis z doubles as split-K axis when
// sA/sB are set to K-chunk offsets and sC to a partial-buffer stride.
// ===========================================================================
template<int BN, bool NN, bool COMP>
__global__ __launch_bounds__(256)
void tgemm(const float* __restrict__ A, const float* __restrict__ B,
           float* __restrict__ C, const float* __restrict__ B2,
           float* __restrict__ C2, int K,
           int lda, int ldb, int ldc, long sA, long sB, long sC, int nb1)
{
    constexpr int BM = 128, AW = BM * 20, BW = BN * 20;
    constexpr int NF = BN / 16;
    constexpr int STG = (COMP ? 2 : 1) * (AW + BW);   // words per stage
    constexpr int NB64 = BN / 64;
    extern __shared__ uint32_t sh[];

    const int z = blockIdx.z;
    A += (long)z * sA;
    const float* Bp = B;  float* Cp = C;
    int by = blockIdx.y;
    if (by >= nb1) { Bp = B2; Cp = C2; by -= nb1; }
    Bp += (long)z * sB;  Cp += (long)z * sC;

    const int m0 = blockIdx.x * BM, n0 = by * BN;
    const int t = threadIdx.x;
    const int wid = t >> 5, g = (t & 31) >> 2, tid = t & 3;
    const int wm = wid >> 1, wn = wid & 1;

    float acc[2][NF][4];
    #pragma unroll
    for (int i = 0; i < 2; i++)
        #pragma unroll
        for (int j = 0; j < NF; j++)
            #pragma unroll
            for (int q = 0; q < 4; q++) acc[i][j][q] = 0.f;

    float4 aR[2], bR[NB64 > 0 ? NB64 : 1];

    // ---- prefetch / store helpers (inlined twice) ----
    auto loadTile = [&](int k0) {
        #pragma unroll
        for (int i = 0; i < 2; i++) {
            int idx = t + i * 256;
            int r = idx >> 2, cg = (idx & 3) * 4;
            aR[i] = *(const float4*)(A + (long)(m0 + r) * lda + k0 + cg);
        }
        if (!NN) {
            #pragma unroll
            for (int i = 0; i < NB64; i++) {
                int idx = t + i * 256;
                int r = idx >> 2, cg = (idx & 3) * 4;
                bR[i] = *(const float4*)(Bp + (long)(n0 + r) * ldb + k0 + cg);
            }
        } else {
            #pragma unroll
            for (int i = 0; i < NB64; i++) {
                int idx = t + i * 256;
                int kr = idx >> (BN == 64 ? 4 : 5);
                int nn = (idx & (BN / 4 - 1)) * 4;
                bR[i] = *(const float4*)(Bp + (long)(k0 + kr) * ldb + n0 + nn);
            }
        }
    };
    auto storeTile = [&](int s) {
        uint32_t* Ah = sh + s * STG;
        uint32_t* Bh = Ah + AW;
        uint32_t* Al = Bh + BW;
        uint32_t* Bl = Al + AW;
        #pragma unroll
        for (int i = 0; i < 2; i++) {
            int idx = t + i * 256;
            int r = idx >> 2, cg = (idx & 3) * 4;
            float4 v = aR[i];
            uint4 h; h.x = f2tf(v.x); h.y = f2tf(v.y); h.z = f2tf(v.z); h.w = f2tf(v.w);
            *(uint4*)(Ah + r * 20 + cg) = h;
            if (COMP) {
                uint4 l;
                l.x = f2tf(v.x - __uint_as_float(h.x));
                l.y = f2tf(v.y - __uint_as_float(h.y));
                l.z = f2tf(v.z - __uint_as_float(h.z));
                l.w = f2tf(v.w - __uint_as_float(h.w));
                *(uint4*)(Al + r * 20 + cg) = l;
            }
        }
        if (!NN) {
            #pragma unroll
            for (int i = 0; i < NB64; i++) {
                int idx = t + i * 256;
                int r = idx >> 2, cg = (idx & 3) * 4;
                float4 v = bR[i];
                uint4 h; h.x = f2tf(v.x); h.y = f2tf(v.y); h.z = f2tf(v.z); h.w = f2tf(v.w);
                *(uint4*)(Bh + r * 20 + cg) = h;
                if (COMP) {
                    uint4 l;
                    l.x = f2tf(v.x - __uint_as_float(h.x));
                    l.y = f2tf(v.y - __uint_as_float(h.y));
                    l.z = f2tf(v.z - __uint_as_float(h.z));
                    l.w = f2tf(v.w - __uint_as_float(h.w));
                    *(uint4*)(Bl + r * 20 + cg) = l;
                }
            }
        } else {
            #pragma unroll
            for (int i = 0; i < NB64; i++) {
                int idx = t + i * 256;
                int kr = idx >> (BN == 64 ? 4 : 5);
                int nn = (idx & (BN / 4 - 1)) * 4;
                float4 v = bR[i];
                Bh[(nn + 0) * 20 + kr] = f2tf(v.x);
                Bh[(nn + 1) * 20 + kr] = f2tf(v.y);
                Bh[(nn + 2) * 20 + kr] = f2tf(v.z);
                Bh[(nn + 3) * 20 + kr] = f2tf(v.w);
            }
        }
    };

    const int nk = K / 16;
    loadTile(0);
    storeTile(0);
    __syncthreads();

    for (int it = 0; it < nk; it++) {
        if (it + 1 < nk) loadTile(16 * (it + 1));

        const uint32_t* Ah = sh + (it & 1) * STG;
        const uint32_t* Bh = Ah + AW;
        const uint32_t* Al = Bh + BW;
        const uint32_t* Bl = Al + AW;

        #pragma unroll
        for (int s = 0; s < 2; s++) {
            const int kk = 8 * s + tid;
            uint32_t ah[2][4], al[2][4];
            #pragma unroll
            for (int mf = 0; mf < 2; mf++) {
                int r = wm * 32 + 16 * mf + g;
                ah[mf][0] = Ah[r * 20 + kk];       ah[mf][1] = Ah[(r + 8) * 20 + kk];
                ah[mf][2] = Ah[r * 20 + kk + 4];   ah[mf][3] = Ah[(r + 8) * 20 + kk + 4];
                if (COMP) {
                    al[mf][0] = Al[r * 20 + kk];     al[mf][1] = Al[(r + 8) * 20 + kk];
                    al[mf][2] = Al[r * 20 + kk + 4]; al[mf][3] = Al[(r + 8) * 20 + kk + 4];
                }
            }
            uint32_t bh[NF][2], bl[NF][2];
            #pragma unroll
            for (int nf = 0; nf < NF; nf++) {
                int n = wn * (BN / 2) + 8 * nf + g;
                bh[nf][0] = Bh[n * 20 + kk];  bh[nf][1] = Bh[n * 20 + kk + 4];
                if (COMP) { bl[nf][0] = Bl[n * 20 + kk]; bl[nf][1] = Bl[n * 20 + kk + 4]; }
            }
            #pragma unroll
            for (int mf = 0; mf < 2; mf++)
                #pragma unroll
                for (int nf = 0; nf < NF; nf++) {
                    mma_tf32(acc[mf][nf], ah[mf], bh[nf]);
                    if (COMP) {
                        mma_tf32(acc[mf][nf], ah[mf], bl[nf]);
                        mma_tf32(acc[mf][nf], al[mf], bh[nf]);
                    }
                }
        }

        if (it + 1 < nk) storeTile((it + 1) & 1);
        __syncthreads();
    }

    #pragma unroll
    for (int mf = 0; mf < 2; mf++) {
        const int r0 = m0 + wm * 32 + 16 * mf + g;
        #pragma unroll
        for (int nf = 0; nf < NF; nf++) {
            const int c = n0 + wn * (BN / 2) + 8 * nf + 2 * tid;
            *(float2*)(Cp + (long)r0 * ldc + c)       = make_float2(acc[mf][nf][0], acc[mf][nf][1]);
            *(float2*)(Cp + (long)(r0 + 8) * ldc + c) = make_float2(acc[mf][nf][2], acc[mf][nf][3]);
        }
    }
}

// Split-K partial reduction: dst[i] = sum_p src[i + p*pstride]   (float4-wide)
__global__ __launch_bounds__(256)
void reduce_add(const float* __restrict__ src, float* __restrict__ dst,
                int n4, int parts, long pstride4)
{
    int i = blockIdx.x * blockDim.x + threadIdx.x;
    if (i >= n4) return;
    const float4* s = (const float4*)src;
    float4 acc = s[i];
    for (int p = 1; p < parts; p++) {
        float4 v = s[i + (long)p * pstride4];
        acc.x += v.x; acc.y += v.y; acc.z += v.z; acc.w += v.w;
    }
    ((float4*)dst)[i] = acc;
}

// ===========================================================================
// Tiny fp32-exact precompute kernels (unchanged)
// ===========================================================================
__global__ __launch_bounds__(128)
void pk_kernel(const float* __restrict__ W_uq, const float* __restrict__ W_uk,
               float* __restrict__ P)
{
    const int i = blockIdx.x, j = threadIdx.x;
    float s = 0.f;
    #pragma unroll 8
    for (int c = 0; c < 1024; c++)
        s += W_uq[c * 128 + i] * W_uk[c * 128 + j];
    P[i * 128 + j] = s;
}
__global__ __launch_bounds__(128)
void m_kernel(const float* __restrict__ W_dq, const float* __restrict__ P,
              float* __restrict__ M)
{
    const int c = blockIdx.x, j = threadIdx.x;
    float s = 0.f;
    #pragma unroll 8
    for (int i = 0; i < 128; i++)
        s += W_dq[i * 1024 + c] * P[i * 128 + j];
    M[c * 128 + j] = s;
}
__global__ __launch_bounds__(128)
void n_kernel(const float* __restrict__ W_uq, const float* __restrict__ M,
              float* __restrict__ Nt)
{
    const int j = blockIdx.x, h = blockIdx.y, i = threadIdx.x;
    float s = 0.f;
    #pragma unroll 8
    for (int d = 0; d < 64; d++)
        s += W_uq[(h * 64 + d) * 128 + i] * M[(h * 64 + d) * 128 + j];
    Nt[(h * 128 + j) * 128 + i] = s;
}

// ===========================================================================
// mma.sync tf32 flash attention v4 (unchanged from R7)
// ===========================================================================
#define AT_K1 0                  // 64 x 132
#define AT_K2 8448               // 64 x 136
#define AT_PS 17152              // 64 x 68
#define AT_WORDS 21504           // 86016 bytes

__global__ __launch_bounds__(128, 2)
void attn4_kernel(const float* __restrict__ ql, const float* __restrict__ ckv,
                  float* __restrict__ ctx)
{
    extern __shared__ uint32_t smu[];
    const int t = threadIdx.x;
    const int w = t >> 5, lid = t & 31;
    const int g = lid >> 2, tid = lid & 3;

    const int h  = blockIdx.x;
    const int qt = 31 - blockIdx.y;
    const int b  = blockIdx.z;
    const long qbase = ((long)h * BT + (long)b * Tt + (long)qt * 64) * 128;
    const long kbase = (long)b * Tt * 128;

    const int rl0 = 16 * w + g;

    uint32_t qf[16][4];
    {
        const float* qr0 = ql + qbase + (long)rl0 * 128;
        const float* qr1 = qr0 + 8 * 128;
        #pragma unroll
        for (int ks = 0; ks < 16; ks++) {
            const int c0 = 8 * ks + tid;
            qf[ks][0] = f2tf(qr0[c0]     * 0.125f);
            qf[ks][1] = f2tf(qr1[c0]     * 0.125f);
            qf[ks][2] = f2tf(qr0[c0 + 4] * 0.125f);
            qf[ks][3] = f2tf(qr1[c0 + 4] * 0.125f);
        }
    }

    float oacc[16][4];
    #pragma unroll
    for (int nb = 0; nb < 16; nb++)
        #pragma unroll
        for (int q = 0; q < 4; q++) oacc[nb][q] = 0.f;

    float m_run[2] = { -1e30f, -1e30f };
    float l_run[2] = { 0.f, 0.f };

    for (int kt = 0; kt <= qt; kt++) {
        __syncthreads();
        {
            const float* ks = ckv + kbase + (long)kt * 64 * 128;
            #pragma unroll
            for (int i = 0; i < 16; i++) {
                int idx = t + i * 128;
                int r = idx >> 5, c = (idx & 31) * 4;
                float4 v = *(const float4*)(ks + (long)r * 128 + c);
                uint4 u;
                u.x = f2tf(v.x); u.y = f2tf(v.y); u.z = f2tf(v.z); u.w = f2tf(v.w);
                *(uint4*)(smu + AT_K1 + r * 132 + c) = u;
                *(uint4*)(smu + AT_K2 + r * 136 + c) = u;
            }
        }
        __syncthreads();

        float sacc[8][4];
        #pragma unroll
        for (int nb = 0; nb < 8; nb++)
            #pragma unroll
            for (int q = 0; q < 4; q++) sacc[nb][q] = 0.f;

        #pragma unroll
        for (int ks = 0; ks < 16; ks++) {
            const int d0 = 8 * ks + tid;
            #pragma unroll
            for (int nb = 0; nb < 8; nb++) {
                uint32_t bf[2];
                bf[0] = smu[AT_K1 + (8 * nb + g) * 132 + d0];
                bf[1] = smu[AT_K1 + (8 * nb + g) * 132 + d0 + 4];
                mma_tf32(sacc[nb], qf[ks], bf);
            }
        }

        if (kt == qt) {
            #pragma unroll
            for (int nb = 0; nb < 8; nb++)
                #pragma unroll
                for (int j = 0; j < 2; j++) {
                    const int col = 8 * nb + 2 * tid + j;
                    if (col > rl0)     sacc[nb][j]     = -1e30f;
                    if (col > rl0 + 8) sacc[nb][2 + j] = -1e30f;
                }
        }

        #pragma unroll
        for (int hh = 0; hh < 2; hh++) {
            float mt = -1e30f;
            #pragma unroll
            for (int nb = 0; nb < 8; nb++)
                mt = fmaxf(mt, fmaxf(sacc[nb][2 * hh], sacc[nb][2 * hh + 1]));
            mt = fmaxf(mt, __shfl_xor_sync(0xffffffffu, mt, 1));
            mt = fmaxf(mt, __shfl_xor_sync(0xffffffffu, mt, 2));

            const float mn = fmaxf(m_run[hh], mt);
            const float sc = __expf(m_run[hh] - mn);
            float ls = 0.f;
            const int rl = rl0 + 8 * hh;
            #pragma unroll
            for (int nb = 0; nb < 8; nb++) {
                float p0 = __expf(sacc[nb][2 * hh]     - mn);
                float p1 = __expf(sacc[nb][2 * hh + 1] - mn);
                ls += p0 + p1;
                uint2 u; u.x = f2tf(p0); u.y = f2tf(p1);
                *(uint2*)(smu + AT_PS + rl * 68 + 8 * nb + 2 * tid) = u;
            }
            ls += __shfl_xor_sync(0xffffffffu, ls, 1);
            ls += __shfl_xor_sync(0xffffffffu, ls, 2);
            l_run[hh] = l_run[hh] * sc + ls;
            m_run[hh] = mn;
            #pragma unroll
            for (int nb = 0; nb < 16; nb++) {
                oacc[nb][2 * hh]     *= sc;
                oacc[nb][2 * hh + 1] *= sc;
            }
        }
        __syncwarp();

        #pragma unroll
        for (int ks = 0; ks < 8; ks++) {
            const int s0 = 8 * ks + tid;
            uint32_t af[4];
            af[0] = smu[AT_PS + rl0 * 68 + s0];
            af[1] = smu[AT_PS + (rl0 + 8) * 68 + s0];
            af[2] = smu[AT_PS + rl0 * 68 + s0 + 4];
            af[3] = smu[AT_PS + (rl0 + 8) * 68 + s0 + 4];
            #pragma unroll
            for (int nb = 0; nb < 16; nb++) {
                uint32_t bf[2];
                bf[0] = smu[AT_K2 + s0 * 136 + 8 * nb + g];
                bf[1] = smu[AT_K2 + (s0 + 4) * 136 + 8 * nb + g];
                mma_tf32(oacc[nb], af, bf);
            }
        }
    }

    #pragma unroll
    for (int hh = 0; hh < 2; hh++) {
        const int rl = rl0 + 8 * hh;
        const float inv = 1.f / l_run[hh];
        float* dst = ctx + qbase + (long)rl * 128;
        #pragma unroll
        for (int nb = 0; nb < 16; nb++)
            *(float2*)(dst + 8 * nb + 2 * tid) =
                make_float2(oacc[nb][2 * hh] * inv, oacc[nb][2 * hh + 1] * inv);
    }
}

// ===========================================================================
extern "C" void kernel_launch(void* const* d_in, const int* in_sizes, int n_in,
                              void* d_out, int out_size)
{
    const float* x     = (const float*)d_in[0];
    const float* W_dq  = (const float*)d_in[1];
    const float* W_uq  = (const float*)d_in[2];
    const float* W_dkv = (const float*)d_in[3];
    const float* W_uk  = (const float*)d_in[4];
    const float* W_uv  = (const float*)d_in[5];
    const float* W_o   = (const float*)d_in[6];

    float* y   = (float*)d_out;
    float* ckv = y + (long)BT * Cc;

    float *P, *M, *Nt, *R, *Aq, *QLp, *CT;
    cudaGetSymbolAddress((void**)&P,  g_P);
    cudaGetSymbolAddress((void**)&M,  g_M);
    cudaGetSymbolAddress((void**)&Nt, g_Nt);
    cudaGetSymbolAddress((void**)&R,  g_R);
    cudaGetSymbolAddress((void**)&Aq, g_Aq);
    cudaGetSymbolAddress((void**)&QLp, g_ql);
    cudaGetSymbolAddress((void**)&CT, g_ct);

    const int NONE = 1 << 30;
    // double-buffered smem sizes (2 stages)
    const size_t S64   = 2 * (128 * 20 + 64 * 20) * 4;        // 30720
    const size_t S128  = 2 * (128 * 20 + 128 * 20) * 4;       // 40960
    const size_t S64C  = 2 * 2 * (128 * 20 + 64 * 20) * 4;    // 61440

    cudaFuncSetAttribute((const void*)tgemm<64, false, true>,
                         cudaFuncAttributeMaxDynamicSharedMemorySize, (int)S64C);
    cudaFuncSetAttribute((const void*)tgemm<128, false, false>,
                         cudaFuncAttributeMaxDynamicSharedMemorySize, (int)S128);
    cudaFuncSetAttribute((const void*)tgemm<64, true, false>,
                         cudaFuncAttributeMaxDynamicSharedMemorySize, (int)S64);
    cudaFuncSetAttribute((const void*)tgemm<64, false, false>,
                         cudaFuncAttributeMaxDynamicSharedMemorySize, (int)S64);

    // Exact fp32 precompute chain: P -> M -> Nt
    pk_kernel<<<128, 128>>>(W_uq, W_uk, P);
    m_kernel<<<1024, 128>>>(W_dq, P, M);
    n_kernel<<<dim3(128, 16), 128>>>(W_uq, M, Nt);

    // Fused x-GEMM, split-K=2: partials for Aq in CT[0..2*524288),
    // partials for ckv in CT[2*524288..4*524288)
    {
        const long PS = (long)BT * 128;                        // 524288
        tgemm<64, false, true><<<dim3(32, 4, 2), 256, S64C>>>(
            x, W_dq, CT, W_dkv, CT + 2 * PS, 512,
            1024, 1024, 128, /*sA=*/512, /*sB=*/512, /*sC=*/PS, 2);
        reduce_add<<<512, 256>>>(CT,          Aq,  (int)(PS / 4), 2, PS / 4);
        reduce_add<<<512, 256>>>(CT + 2 * PS, ckv, (int)(PS / 4), 2, PS / 4);
    }

    // R = W_o @ W_uv, split-K=4: partials in CT[0..4*131072)
    {
        const long PR = 1024 * 128;                            // 131072
        tgemm<64, true, false><<<dim3(8, 2, 4), 256, S64>>>(
            W_o, W_uv, CT, nullptr, nullptr, 256,
            1024, 128, 128, /*sA=*/256, /*sB=*/256 * 128, /*sC=*/PR, NONE);
        reduce_add<<<128, 256>>>(CT, R, (int)(PR / 4), 4, PR / 4);
    }

    // ql[h] = Aq @ N[h]   (batched 16, K=128)
    tgemm<128, false, false><<<dim3(32, 1, 16), 256, S128>>>(
        Aq, Nt, QLp, nullptr, nullptr, 128, 128, 128, 128,
        0, 128 * 128, (long)BT * 128, NONE);

    // flash attention -> ctx   (overwrites CT scratch; partials already consumed)
    cudaFuncSetAttribute(attn4_kernel, cudaFuncAttributeMaxDynamicSharedMemorySize,
                         AT_WORDS * 4);
    attn4_kernel<<<dim3(16, 32, 2), 128, AT_WORDS * 4>>>(QLp, ckv, CT);

    // y[:, h*64:] = ctx[h] @ R[h*64:, :]^T   (batched 16, K=128, N=64)
    tgemm<64, false, false><<<dim3(32, 1, 16), 256, S64>>>(
        CT, R, y, nullptr, nullptr, 128, 128, 128, 1024,
        (long)BT * 128, 64 * 128, 64, NONE);
}

// round 9
// speedup vs baseline: 1.9079x; 1.1509x over previous
#include <cuda_runtime.h>
#include <cuda_fp16.h>
#include <cstdint>

// Problem constants (fixed by setup_inputs)
#define Bb    2
#define Tt    2048
#define Cc    1024
#define QLd   128
#define KVL   128
#define NHh   16
#define HSd   64
#define BT    (Bb*Tt)          // 4096

// Scratch (device globals: no allocation allowed)
__device__ float g_P [QLd*KVL];          // W_uq^T @ W_uk          (128,128)
__device__ float g_M [Cc*KVL];           // W_dq^T @ P             (1024,128)
__device__ float g_Nt[NHh*KVL*QLd];      // Nt[h][j][i] = N[h][i][j]
__device__ float g_R [Cc*KVL];           // W_o @ W_uv             (1024,128)
__device__ float g_Aq[BT*QLd];           // x @ W_dq^T             (4096,128)
__device__ float g_ql[NHh*BT*KVL];       // latent queries         (16,4096,128)
__device__ float g_ct[NHh*BT*KVL];       // latent context (also GEMM partial scratch)

__device__ __forceinline__ uint32_t f2tf(float f) {
    uint32_t u;
    asm("cvt.rna.tf32.f32 %0, %1;" : "=r"(u) : "f"(f));
    return u;
}
__device__ __forceinline__ uint32_t f2h2(float a, float b) {
    __half2 h = __floats2half2_rn(a, b);
    return *(uint32_t*)&h;
}
__device__ __forceinline__ void mma_tf32(float* d, const uint32_t* a, const uint32_t* b) {
    asm volatile(
        "mma.sync.aligned.m16n8k8.row.col.f32.tf32.tf32.f32 "
        "{%0,%1,%2,%3}, {%4,%5,%6,%7}, {%8,%9}, {%0,%1,%2,%3};"
        : "+f"(d[0]), "+f"(d[1]), "+f"(d[2]), "+f"(d[3])
        : "r"(a[0]), "r"(a[1]), "r"(a[2]), "r"(a[3]), "r"(b[0]), "r"(b[1]));
}
__device__ __forceinline__ void mma_f16(float* d, const uint32_t* a, uint32_t b0, uint32_t b1) {
    asm volatile(
        "mma.sync.aligned.m16n8k16.row.col.f32.f16.f16.f32 "
        "{%0,%1,%2,%3}, {%4,%5,%6,%7}, {%8,%9}, {%0,%1,%2,%3};"
        : "+f"(d[0]), "+f"(d[1]), "+f"(d[2]), "+f"(d[3])
        : "r"(a[0]), "r"(a[1]), "r"(a[2]), "r"(a[3]), "r"(b0), "r"(b1));
}

// ===========================================================================
// tf32 tensor-core GEMM, software-pipelined (unchanged from R8)
// ===========================================================================
template<int BN, bool NN, bool COMP>
__global__ __launch_bounds__(256)
void tgemm(const float* __restrict__ A, const float* __restrict__ B,
           float* __restrict__ C, const float* __restrict__ B2,
           float* __restrict__ C2, int K,
           int lda, int ldb, int ldc, long sA, long sB, long sC, int nb1)
{
    constexpr int BM = 128, AW = BM * 20, BW = BN * 20;
    constexpr int NF = BN / 16;
    constexpr int STG = (COMP ? 2 : 1) * (AW + BW);
    constexpr int NB64 = BN / 64;
    extern __shared__ uint32_t sh[];

    const int z = blockIdx.z;
    A += (long)z * sA;
    const float* Bp = B;  float* Cp = C;
    int by = blockIdx.y;
    if (by >= nb1) { Bp = B2; Cp = C2; by -= nb1; }
    Bp += (long)z * sB;  Cp += (long)z * sC;

    const int m0 = blockIdx.x * BM, n0 = by * BN;
    const int t = threadIdx.x;
    const int wid = t >> 5, g = (t & 31) >> 2, tid = t & 3;
    const int wm = wid >> 1, wn = wid & 1;

    float acc[2][NF][4];
    #pragma unroll
    for (int i = 0; i < 2; i++)
        #pragma unroll
        for (int j = 0; j < NF; j++)
            #pragma unroll
            for (int q = 0; q < 4; q++) acc[i][j][q] = 0.f;

    float4 aR[2], bR[NB64 > 0 ? NB64 : 1];

    auto loadTile = [&](int k0) {
        #pragma unroll
        for (int i = 0; i < 2; i++) {
            int idx = t + i * 256;
            int r = idx >> 2, cg = (idx & 3) * 4;
            aR[i] = *(const float4*)(A + (long)(m0 + r) * lda + k0 + cg);
        }
        if (!NN) {
            #pragma unroll
            for (int i = 0; i < NB64; i++) {
                int idx = t + i * 256;
                int r = idx >> 2, cg = (idx & 3) * 4;
                bR[i] = *(const float4*)(Bp + (long)(n0 + r) * ldb + k0 + cg);
            }
        } else {
            #pragma unroll
            for (int i = 0; i < NB64; i++) {
                int idx = t + i * 256;
                int kr = idx >> (BN == 64 ? 4 : 5);
                int nn = (idx & (BN / 4 - 1)) * 4;
                bR[i] = *(const float4*)(Bp + (long)(k0 + kr) * ldb + n0 + nn);
            }
        }
    };
    auto storeTile = [&](int s) {
        uint32_t* Ah = sh + s * STG;
        uint32_t* Bh = Ah + AW;
        uint32_t* Al = Bh + BW;
        uint32_t* Bl = Al + AW;
        #pragma unroll
        for (int i = 0; i < 2; i++) {
            int idx = t + i * 256;
            int r = idx >> 2, cg = (idx & 3) * 4;
            float4 v = aR[i];
            uint4 h; h.x = f2tf(v.x); h.y = f2tf(v.y); h.z = f2tf(v.z); h.w = f2tf(v.w);
            *(uint4*)(Ah + r * 20 + cg) = h;
            if (COMP) {
                uint4 l;
                l.x = f2tf(v.x - __uint_as_float(h.x));
                l.y = f2tf(v.y - __uint_as_float(h.y));
                l.z = f2tf(v.z - __uint_as_float(h.z));
                l.w = f2tf(v.w - __uint_as_float(h.w));
                *(uint4*)(Al + r * 20 + cg) = l;
            }
        }
        if (!NN) {
            #pragma unroll
            for (int i = 0; i < NB64; i++) {
                int idx = t + i * 256;
                int r = idx >> 2, cg = (idx & 3) * 4;
                float4 v = bR[i];
                uint4 h; h.x = f2tf(v.x); h.y = f2tf(v.y); h.z = f2tf(v.z); h.w = f2tf(v.w);
                *(uint4*)(Bh + r * 20 + cg) = h;
                if (COMP) {
                    uint4 l;
                    l.x = f2tf(v.x - __uint_as_float(h.x));
                    l.y = f2tf(v.y - __uint_as_float(h.y));
                    l.z = f2tf(v.z - __uint_as_float(h.z));
                    l.w = f2tf(v.w - __uint_as_float(h.w));
                    *(uint4*)(Bl + r * 20 + cg) = l;
                }
            }
        } else {
            #pragma unroll
            for (int i = 0; i < NB64; i++) {
                int idx = t + i * 256;
                int kr = idx >> (BN == 64 ? 4 : 5);
                int nn = (idx & (BN / 4 - 1)) * 4;
                float4 v = bR[i];
                Bh[(nn + 0) * 20 + kr] = f2tf(v.x);
                Bh[(nn + 1) * 20 + kr] = f2tf(v.y);
                Bh[(nn + 2) * 20 + kr] = f2tf(v.z);
                Bh[(nn + 3) * 20 + kr] = f2tf(v.w);
            }
        }
    };

    const int nk = K / 16;
    loadTile(0);
    storeTile(0);
    __syncthreads();

    for (int it = 0; it < nk; it++) {
        if (it + 1 < nk) loadTile(16 * (it + 1));

        const uint32_t* Ah = sh + (it & 1) * STG;
        const uint32_t* Bh = Ah + AW;
        const uint32_t* Al = Bh + BW;
        const uint32_t* Bl = Al + AW;

        #pragma unroll
        for (int s = 0; s < 2; s++) {
            const int kk = 8 * s + tid;
            uint32_t ah[2][4], al[2][4];
            #pragma unroll
            for (int mf = 0; mf < 2; mf++) {
                int r = wm * 32 + 16 * mf + g;
                ah[mf][0] = Ah[r * 20 + kk];       ah[mf][1] = Ah[(r + 8) * 20 + kk];
                ah[mf][2] = Ah[r * 20 + kk + 4];   ah[mf][3] = Ah[(r + 8) * 20 + kk + 4];
                if (COMP) {
                    al[mf][0] = Al[r * 20 + kk];     al[mf][1] = Al[(r + 8) * 20 + kk];
                    al[mf][2] = Al[r * 20 + kk + 4]; al[mf][3] = Al[(r + 8) * 20 + kk + 4];
                }
            }
            uint32_t bh[NF][2], bl[NF][2];
            #pragma unroll
            for (int nf = 0; nf < NF; nf++) {
                int n = wn * (BN / 2) + 8 * nf + g;
                bh[nf][0] = Bh[n * 20 + kk];  bh[nf][1] = Bh[n * 20 + kk + 4];
                if (COMP) { bl[nf][0] = Bl[n * 20 + kk]; bl[nf][1] = Bl[n * 20 + kk + 4]; }
            }
            #pragma unroll
            for (int mf = 0; mf < 2; mf++)
                #pragma unroll
                for (int nf = 0; nf < NF; nf++) {
                    mma_tf32(acc[mf][nf], ah[mf], bh[nf]);
                    if (COMP) {
                        mma_tf32(acc[mf][nf], ah[mf], bl[nf]);
                        mma_tf32(acc[mf][nf], al[mf], bh[nf]);
                    }
                }
        }

        if (it + 1 < nk) storeTile((it + 1) & 1);
        __syncthreads();
    }

    #pragma unroll
    for (int mf = 0; mf < 2; mf++) {
        const int r0 = m0 + wm * 32 + 16 * mf + g;
        #pragma unroll
        for (int nf = 0; nf < NF; nf++) {
            const int c = n0 + wn * (BN / 2) + 8 * nf + 2 * tid;
            *(float2*)(Cp + (long)r0 * ldc + c)       = make_float2(acc[mf][nf][0], acc[mf][nf][1]);
            *(float2*)(Cp + (long)(r0 + 8) * ldc + c) = make_float2(acc[mf][nf][2], acc[mf][nf][3]);
        }
    }
}

// Split-K partial reduction (float4-wide)
__global__ __launch_bounds__(256)
void reduce_add(const float* __restrict__ src, float* __restrict__ dst,
                int n4, int parts, long pstride4)
{
    int i = blockIdx.x * blockDim.x + threadIdx.x;
    if (i >= n4) return;
    const float4* s = (const float4*)src;
    float4 acc = s[i];
    for (int p = 1; p < parts; p++) {
        float4 v = s[i + (long)p * pstride4];
        acc.x += v.x; acc.y += v.y; acc.z += v.z; acc.w += v.w;
    }
    ((float4*)dst)[i] = acc;
}

// ===========================================================================
// Tiny fp32-exact precompute kernels (unchanged)
// ===========================================================================
__global__ __launch_bounds__(128)
void pk_kernel(const float* __restrict__ W_uq, const float* __restrict__ W_uk,
               float* __restrict__ P)
{
    const int i = blockIdx.x, j = threadIdx.x;
    float s = 0.f;
    #pragma unroll 8
    for (int c = 0; c < 1024; c++)
        s += W_uq[c * 128 + i] * W_uk[c * 128 + j];
    P[i * 128 + j] = s;
}
__global__ __launch_bounds__(128)
void m_kernel(const float* __restrict__ W_dq, const float* __restrict__ P,
              float* __restrict__ M)
{
    const int c = blockIdx.x, j = threadIdx.x;
    float s = 0.f;
    #pragma unroll 8
    for (int i = 0; i < 128; i++)
        s += W_dq[i * 1024 + c] * P[i * 128 + j];
    M[c * 128 + j] = s;
}
__global__ __launch_bounds__(128)
void n_kernel(const float* __restrict__ W_uq, const float* __restrict__ M,
              float* __restrict__ Nt)
{
    const int j = blockIdx.x, h = blockIdx.y, i = threadIdx.x;
    float s = 0.f;
    #pragma unroll 8
    for (int d = 0; d < 64; d++)
        s += W_uq[(h * 64 + d) * 128 + i] * M[(h * 64 + d) * 128 + j];
    Nt[(h * 128 + j) * 128 + i] = s;
}

// ===========================================================================
// fp16 mma flash attention v5.
// Same 10-bit mantissa as tf32 -> numerics unchanged; 2x MMA rate; half the
// B-fragment bytes on the smem crossbar (the binding resource).
// K1: half2 s-major (stride 68 words)  - S-phase B, conflict-free.
// KT: half2 d-major (stride 37 words)  - PV B, near-conflict-free; built by a
//     second column-patterned gmem read (L2-hot).
// PS: half2 P tiles (stride 36 words).
// 45.5 KB smem, 128 thr, 2 CTAs/SM.
// ===========================================================================
#define A5_K1 0                      // 64 x 68 words
#define A5_KT (64 * 68)              // 128 x 37 words
#define A5_PS (64 * 68 + 128 * 37)   // 64 x 36 words
#define A5_WORDS (64 * 68 + 128 * 37 + 64 * 36)   // 11392 words = 45568 B

__global__ __launch_bounds__(128, 2)
void attn5_kernel(const float* __restrict__ ql, const float* __restrict__ ckv,
                  float* __restrict__ ctx)
{
    extern __shared__ uint32_t smu[];
    const int t = threadIdx.x;
    const int w = t >> 5, lid = t & 31;
    const int g = lid >> 2, tid = lid & 3;

    const int h  = blockIdx.x;               // fastest: K-tile L2 sharing
    const int qt = 31 - blockIdx.y;          // heavy tiles first
    const int b  = blockIdx.z;
    const long qbase = ((long)h * BT + (long)b * Tt + (long)qt * 64) * 128;
    const long kbase = (long)b * Tt * 128;

    const int rl0 = 16 * w + g;              // local query row (0..63)

    // ---- Q A-fragments (fp16, prescaled by 1/8) -> 32 registers ----
    uint32_t qf[8][4];
    {
        const float* qr0 = ql + qbase + (long)rl0 * 128;
        const float* qr1 = qr0 + 8 * 128;
        #pragma unroll
        for (int kb = 0; kb < 8; kb++) {
            const int c = 16 * kb + 2 * tid;
            float2 v00 = *(const float2*)(qr0 + c);
            float2 v10 = *(const float2*)(qr1 + c);
            float2 v01 = *(const float2*)(qr0 + c + 8);
            float2 v11 = *(const float2*)(qr1 + c + 8);
            qf[kb][0] = f2h2(v00.x * 0.125f, v00.y * 0.125f);
            qf[kb][1] = f2h2(v10.x * 0.125f, v10.y * 0.125f);
            qf[kb][2] = f2h2(v01.x * 0.125f, v01.y * 0.125f);
            qf[kb][3] = f2h2(v11.x * 0.125f, v11.y * 0.125f);
        }
    }

    float oacc[16][4];
    #pragma unroll
    for (int nb = 0; nb < 16; nb++)
        #pragma unroll
        for (int q = 0; q < 4; q++) oacc[nb][q] = 0.f;

    float m_run[2] = { -1e30f, -1e30f };
    float l_run[2] = { 0.f, 0.f };

    for (int kt = 0; kt <= qt; kt++) {
        __syncthreads();     // prev phase reads done before K overwrite
        {
            const float* ks = ckv + kbase + (long)kt * 64 * 128;
            // K1: row loader (s-major half2)
            #pragma unroll
            for (int i = 0; i < 16; i++) {
                int idx = t + i * 128;
                int r = idx >> 5, c = (idx & 31) * 4;
                float4 v = *(const float4*)(ks + (long)r * 128 + c);
                uint2 u = make_uint2(f2h2(v.x, v.y), f2h2(v.z, v.w));
                *(uint2*)(smu + A5_K1 + r * 68 + (c >> 1)) = u;
            }
            // KT: column loader (d-major half2); warp w covers d in [32w, 32w+32)
            {
                const int d = 32 * w + lid;
                const float* kc = ks + d;
                #pragma unroll
                for (int s = 0; s < 64; s += 4) {
                    float a0 = kc[(s + 0) * 128];
                    float a1 = kc[(s + 1) * 128];
                    float a2 = kc[(s + 2) * 128];
                    float a3 = kc[(s + 3) * 128];
                    smu[A5_KT + d * 37 + (s >> 1)]     = f2h2(a0, a1);
                    smu[A5_KT + d * 37 + (s >> 1) + 1] = f2h2(a2, a3);
                }
            }
        }
        __syncthreads();

        // ---- S = Q K^T : 8 f16 k-blocks x 8 key-blocks ----
        float sacc[8][4];
        #pragma unroll
        for (int nb = 0; nb < 8; nb++)
            #pragma unroll
            for (int q = 0; q < 4; q++) sacc[nb][q] = 0.f;

        #pragma unroll
        for (int kb = 0; kb < 8; kb++) {
            const int w0 = 8 * kb + tid;
            #pragma unroll
            for (int nb = 0; nb < 8; nb++) {
                uint32_t b0 = smu[A5_K1 + (8 * nb + g) * 68 + w0];
                uint32_t b1 = smu[A5_K1 + (8 * nb + g) * 68 + w0 + 4];
                mma_f16(sacc[nb], qf[kb], b0, b1);
            }
        }

        // ---- causal mask (diagonal tile only) ----
        if (kt == qt) {
            #pragma unroll
            for (int nb = 0; nb < 8; nb++)
                #pragma unroll
                for (int j = 0; j < 2; j++) {
                    const int col = 8 * nb + 2 * tid + j;
                    if (col > rl0)     sacc[nb][j]     = -1e30f;
                    if (col > rl0 + 8) sacc[nb][2 + j] = -1e30f;
                }
        }

        // ---- online softmax; P stored as half2 ----
        #pragma unroll
        for (int hh = 0; hh < 2; hh++) {
            float mt = -1e30f;
            #pragma unroll
            for (int nb = 0; nb < 8; nb++)
                mt = fmaxf(mt, fmaxf(sacc[nb][2 * hh], sacc[nb][2 * hh + 1]));
            mt = fmaxf(mt, __shfl_xor_sync(0xffffffffu, mt, 1));
            mt = fmaxf(mt, __shfl_xor_sync(0xffffffffu, mt, 2));

            const float mn = fmaxf(m_run[hh], mt);
            const float sc = __expf(m_run[hh] - mn);
            float ls = 0.f;
            const int rl = rl0 + 8 * hh;
            #pragma unroll
            for (int nb = 0; nb < 8; nb++) {
                float p0 = __expf(sacc[nb][2 * hh]     - mn);
                float p1 = __expf(sacc[nb][2 * hh + 1] - mn);
                ls += p0 + p1;
                smu[A5_PS + rl * 36 + 4 * nb + tid] = f2h2(p0, p1);
            }
            ls += __shfl_xor_sync(0xffffffffu, ls, 1);
            ls += __shfl_xor_sync(0xffffffffu, ls, 2);
            l_run[hh] = l_run[hh] * sc + ls;
            m_run[hh] = mn;
            #pragma unroll
            for (int nb = 0; nb < 16; nb++) {
                oacc[nb][2 * hh]     *= sc;
                oacc[nb][2 * hh + 1] *= sc;
            }
        }
        __syncwarp();   // P rows are warp-private

        // ---- O += P @ Ktile : 4 f16 k-blocks x 16 d-blocks ----
        #pragma unroll
        for (int kb = 0; kb < 4; kb++) {
            const int w0 = 8 * kb + tid;
            uint32_t af[4];
            af[0] = smu[A5_PS + rl0 * 36 + w0];
            af[1] = smu[A5_PS + (rl0 + 8) * 36 + w0];
            af[2] = smu[A5_PS + rl0 * 36 + w0 + 4];
            af[3] = smu[A5_PS + (rl0 + 8) * 36 + w0 + 4];
            #pragma unroll
            for (int nb = 0; nb < 16; nb++) {
                uint32_t b0 = smu[A5_KT + (8 * nb + g) * 37 + w0];
                uint32_t b1 = smu[A5_KT + (8 * nb + g) * 37 + w0 + 4];
                mma_f16(oacc[nb], af, b0, b1);
            }
        }
    }

    // ---- epilogue: ctx = O / l ----
    #pragma unroll
    for (int hh = 0; hh < 2; hh++) {
        const int rl = rl0 + 8 * hh;
        const float inv = 1.f / l_run[hh];
        float* dst = ctx + qbase + (long)rl * 128;
        #pragma unroll
        for (int nb = 0; nb < 16; nb++)
            *(float2*)(dst + 8 * nb + 2 * tid) =
                make_float2(oacc[nb][2 * hh] * inv, oacc[nb][2 * hh + 1] * inv);
    }
}

// ===========================================================================
extern "C" void kernel_launch(void* const* d_in, const int* in_sizes, int n_in,
                              void* d_out, int out_size)
{
    const float* x     = (const float*)d_in[0];
    const float* W_dq  = (const float*)d_in[1];
    const float* W_uq  = (const float*)d_in[2];
    const float* W_dkv = (const float*)d_in[3];
    const float* W_uk  = (const float*)d_in[4];
    const float* W_uv  = (const float*)d_in[5];
    const float* W_o   = (const float*)d_in[6];

    float* y   = (float*)d_out;
    float* ckv = y + (long)BT * Cc;

    float *P, *M, *Nt, *R, *Aq, *QLp, *CT;
    cudaGetSymbolAddress((void**)&P,  g_P);
    cudaGetSymbolAddress((void**)&M,  g_M);
    cudaGetSymbolAddress((void**)&Nt, g_Nt);
    cudaGetSymbolAddress((void**)&R,  g_R);
    cudaGetSymbolAddress((void**)&Aq, g_Aq);
    cudaGetSymbolAddress((void**)&QLp, g_ql);
    cudaGetSymbolAddress((void**)&CT, g_ct);

    const int NONE = 1 << 30;
    const size_t S64   = 2 * (128 * 20 + 64 * 20) * 4;
    const size_t S128  = 2 * (128 * 20 + 128 * 20) * 4;
    const size_t S64C  = 2 * 2 * (128 * 20 + 64 * 20) * 4;

    cudaFuncSetAttribute((const void*)tgemm<64, false, true>,
                         cudaFuncAttributeMaxDynamicSharedMemorySize, (int)S64C);
    cudaFuncSetAttribute((const void*)tgemm<128, false, false>,
                         cudaFuncAttributeMaxDynamicSharedMemorySize, (int)S128);
    cudaFuncSetAttribute((const void*)tgemm<64, true, false>,
                         cudaFuncAttributeMaxDynamicSharedMemorySize, (int)S64);
    cudaFuncSetAttribute((const void*)tgemm<64, false, false>,
                         cudaFuncAttributeMaxDynamicSharedMemorySize, (int)S64);

    // Exact fp32 precompute chain: P -> M -> Nt
    pk_kernel<<<128, 128>>>(W_uq, W_uk, P);
    m_kernel<<<1024, 128>>>(W_dq, P, M);
    n_kernel<<<dim3(128, 16), 128>>>(W_uq, M, Nt);

    // Fused x-GEMM, split-K=2
    {
        const long PS = (long)BT * 128;
        tgemm<64, false, true><<<dim3(32, 4, 2), 256, S64C>>>(
            x, W_dq, CT, W_dkv, CT + 2 * PS, 512,
            1024, 1024, 128, 512, 512, PS, 2);
        reduce_add<<<512, 256>>>(CT,          Aq,  (int)(PS / 4), 2, PS / 4);
        reduce_add<<<512, 256>>>(CT + 2 * PS, ckv, (int)(PS / 4), 2, PS / 4);
    }

    // R = W_o @ W_uv, split-K=4
    {
        const long PR = 1024 * 128;
        tgemm<64, true, false><<<dim3(8, 2, 4), 256, S64>>>(
            W_o, W_uv, CT, nullptr, nullptr, 256,
            1024, 128, 128, 256, 256 * 128, PR, NONE);
        reduce_add<<<128, 256>>>(CT, R, (int)(PR / 4), 4, PR / 4);
    }

    // ql[h] = Aq @ N[h]   (batched 16, K=128)
    tgemm<128, false, false><<<dim3(32, 1, 16), 256, S128>>>(
        Aq, Nt, QLp, nullptr, nullptr, 128, 128, 128, 128,
        0, 128 * 128, (long)BT * 128, NONE);

    // fp16 flash attention -> ctx
    cudaFuncSetAttribute(attn5_kernel, cudaFuncAttributeMaxDynamicSharedMemorySize,
                         A5_WORDS * 4);
    attn5_kernel<<<dim3(16, 32, 2), 128, A5_WORDS * 4>>>(QLp, ckv, CT);

    // y[:, h*64:] = ctx[h] @ R[h*64:, :]^T   (batched 16, K=128, N=64)
    tgemm<64, false, false><<<dim3(32, 1, 16), 256, S64>>>(
        CT, R, y, nullptr, nullptr, 128, 128, 128, 1024,
        (long)BT * 128, 64 * 128, 64, NONE);
}

// round 10
// speedup vs baseline: 1.9585x; 1.0265x over previous
#include <cuda_runtime.h>
#include <cuda_fp16.h>
#include <cstdint>

// Problem constants (fixed by setup_inputs)
#define Bb    2
#define Tt    2048
#define Cc    1024
#define QLd   128
#define KVL   128
#define NHh   16
#define HSd   64
#define BT    (Bb*Tt)          // 4096

// Scratch (device globals: no allocation allowed)
__device__ float g_P [QLd*KVL];          // W_uq^T @ W_uk          (128,128)
__device__ float g_M [Cc*KVL];           // W_dq^T @ P             (1024,128)
__device__ float g_Nt[NHh*KVL*QLd];      // Nt[h][j][i] = N[h][i][j]
__device__ float g_R [Cc*KVL];           // W_o @ W_uv             (1024,128)
__device__ float g_Aq[BT*QLd];           // x @ W_dq^T             (4096,128)
__device__ float g_ql[NHh*BT*KVL];       // latent queries         (16,4096,128)
__device__ float g_ct[NHh*BT*KVL];       // latent context (also GEMM partial scratch)

__device__ __forceinline__ uint32_t f2tf(float f) {
    uint32_t u;
    asm("cvt.rna.tf32.f32 %0, %1;" : "=r"(u) : "f"(f));
    return u;
}
__device__ __forceinline__ uint32_t f2h2(float a, float b) {
    __half2 h = __floats2half2_rn(a, b);
    return *(uint32_t*)&h;
}
__device__ __forceinline__ void mma_tf32(float* d, const uint32_t* a, const uint32_t* b) {
    asm volatile(
        "mma.sync.aligned.m16n8k8.row.col.f32.tf32.tf32.f32 "
        "{%0,%1,%2,%3}, {%4,%5,%6,%7}, {%8,%9}, {%0,%1,%2,%3};"
        : "+f"(d[0]), "+f"(d[1]), "+f"(d[2]), "+f"(d[3])
        : "r"(a[0]), "r"(a[1]), "r"(a[2]), "r"(a[3]), "r"(b[0]), "r"(b[1]));
}
__device__ __forceinline__ void mma_f16(float* d, const uint32_t* a, uint32_t b0, uint32_t b1) {
    asm volatile(
        "mma.sync.aligned.m16n8k16.row.col.f32.f16.f16.f32 "
        "{%0,%1,%2,%3}, {%4,%5,%6,%7}, {%8,%9}, {%0,%1,%2,%3};"
        : "+f"(d[0]), "+f"(d[1]), "+f"(d[2]), "+f"(d[3])
        : "r"(a[0]), "r"(a[1]), "r"(a[2]), "r"(a[3]), "r"(b0), "r"(b1));
}

// ===========================================================================
// tf32 tensor-core GEMM, software-pipelined (unchanged from R8/R9)
// ===========================================================================
template<int BN, bool NN, bool COMP>
__global__ __launch_bounds__(256)
void tgemm(const float* __restrict__ A, const float* __restrict__ B,
           float* __restrict__ C, const float* __restrict__ B2,
           float* __restrict__ C2, int K,
           int lda, int ldb, int ldc, long sA, long sB, long sC, int nb1)
{
    constexpr int BM = 128, AW = BM * 20, BW = BN * 20;
    constexpr int NF = BN / 16;
    constexpr int STG = (COMP ? 2 : 1) * (AW + BW);
    constexpr int NB64 = BN / 64;
    extern __shared__ uint32_t sh[];

    const int z = blockIdx.z;
    A += (long)z * sA;
    const float* Bp = B;  float* Cp = C;
    int by = blockIdx.y;
    if (by >= nb1) { Bp = B2; Cp = C2; by -= nb1; }
    Bp += (long)z * sB;  Cp += (long)z * sC;

    const int m0 = blockIdx.x * BM, n0 = by * BN;
    const int t = threadIdx.x;
    const int wid = t >> 5, g = (t & 31) >> 2, tid = t & 3;
    const int wm = wid >> 1, wn = wid & 1;

    float acc[2][NF][4];
    #pragma unroll
    for (int i = 0; i < 2; i++)
        #pragma unroll
        for (int j = 0; j < NF; j++)
            #pragma unroll
            for (int q = 0; q < 4; q++) acc[i][j][q] = 0.f;

    float4 aR[2], bR[NB64 > 0 ? NB64 : 1];

    auto loadTile = [&](int k0) {
        #pragma unroll
        for (int i = 0; i < 2; i++) {
            int idx = t + i * 256;
            int r = idx >> 2, cg = (idx & 3) * 4;
            aR[i] = *(const float4*)(A + (long)(m0 + r) * lda + k0 + cg);
        }
        if (!NN) {
            #pragma unroll
            for (int i = 0; i < NB64; i++) {
                int idx = t + i * 256;
                int r = idx >> 2, cg = (idx & 3) * 4;
                bR[i] = *(const float4*)(Bp + (long)(n0 + r) * ldb + k0 + cg);
            }
        } else {
            #pragma unroll
            for (int i = 0; i < NB64; i++) {
                int idx = t + i * 256;
                int kr = idx >> (BN == 64 ? 4 : 5);
                int nn = (idx & (BN / 4 - 1)) * 4;
                bR[i] = *(const float4*)(Bp + (long)(k0 + kr) * ldb + n0 + nn);
            }
        }
    };
    auto storeTile = [&](int s) {
        uint32_t* Ah = sh + s * STG;
        uint32_t* Bh = Ah + AW;
        uint32_t* Al = Bh + BW;
        uint32_t* Bl = Al + AW;
        #pragma unroll
        for (int i = 0; i < 2; i++) {
            int idx = t + i * 256;
            int r = idx >> 2, cg = (idx & 3) * 4;
            float4 v = aR[i];
            uint4 h; h.x = f2tf(v.x); h.y = f2tf(v.y); h.z = f2tf(v.z); h.w = f2tf(v.w);
            *(uint4*)(Ah + r * 20 + cg) = h;
            if (COMP) {
                uint4 l;
                l.x = f2tf(v.x - __uint_as_float(h.x));
                l.y = f2tf(v.y - __uint_as_float(h.y));
                l.z = f2tf(v.z - __uint_as_float(h.z));
                l.w = f2tf(v.w - __uint_as_float(h.w));
                *(uint4*)(Al + r * 20 + cg) = l;
            }
        }
        if (!NN) {
            #pragma unroll
            for (int i = 0; i < NB64; i++) {
                int idx = t + i * 256;
                int r = idx >> 2, cg = (idx & 3) * 4;
                float4 v = bR[i];
                uint4 h; h.x = f2tf(v.x); h.y = f2tf(v.y); h.z = f2tf(v.z); h.w = f2tf(v.w);
                *(uint4*)(Bh + r * 20 + cg) = h;
                if (COMP) {
                    uint4 l;
                    l.x = f2tf(v.x - __uint_as_float(h.x));
                    l.y = f2tf(v.y - __uint_as_float(h.y));
                    l.z = f2tf(v.z - __uint_as_float(h.z));
                    l.w = f2tf(v.w - __uint_as_float(h.w));
                    *(uint4*)(Bl + r * 20 + cg) = l;
                }
            }
        } else {
            #pragma unroll
            for (int i = 0; i < NB64; i++) {
                int idx = t + i * 256;
                int kr = idx >> (BN == 64 ? 4 : 5);
                int nn = (idx & (BN / 4 - 1)) * 4;
                float4 v = bR[i];
                Bh[(nn + 0) * 20 + kr] = f2tf(v.x);
                Bh[(nn + 1) * 20 + kr] = f2tf(v.y);
                Bh[(nn + 2) * 20 + kr] = f2tf(v.z);
                Bh[(nn + 3) * 20 + kr] = f2tf(v.w);
            }
        }
    };

    const int nk = K / 16;
    loadTile(0);
    storeTile(0);
    __syncthreads();

    for (int it = 0; it < nk; it++) {
        if (it + 1 < nk) loadTile(16 * (it + 1));

        const uint32_t* Ah = sh + (it & 1) * STG;
        const uint32_t* Bh = Ah + AW;
        const uint32_t* Al = Bh + BW;
        const uint32_t* Bl = Al + AW;

        #pragma unroll
        for (int s = 0; s < 2; s++) {
            const int kk = 8 * s + tid;
            uint32_t ah[2][4], al[2][4];
            #pragma unroll
            for (int mf = 0; mf < 2; mf++) {
                int r = wm * 32 + 16 * mf + g;
                ah[mf][0] = Ah[r * 20 + kk];       ah[mf][1] = Ah[(r + 8) * 20 + kk];
                ah[mf][2] = Ah[r * 20 + kk + 4];   ah[mf][3] = Ah[(r + 8) * 20 + kk + 4];
                if (COMP) {
                    al[mf][0] = Al[r * 20 + kk];     al[mf][1] = Al[(r + 8) * 20 + kk];
                    al[mf][2] = Al[r * 20 + kk + 4]; al[mf][3] = Al[(r + 8) * 20 + kk + 4];
                }
            }
            uint32_t bh[NF][2], bl[NF][2];
            #pragma unroll
            for (int nf = 0; nf < NF; nf++) {
                int n = wn * (BN / 2) + 8 * nf + g;
                bh[nf][0] = Bh[n * 20 + kk];  bh[nf][1] = Bh[n * 20 + kk + 4];
                if (COMP) { bl[nf][0] = Bl[n * 20 + kk]; bl[nf][1] = Bl[n * 20 + kk + 4]; }
            }
            #pragma unroll
            for (int mf = 0; mf < 2; mf++)
                #pragma unroll
                for (int nf = 0; nf < NF; nf++) {
                    mma_tf32(acc[mf][nf], ah[mf], bh[nf]);
                    if (COMP) {
                        mma_tf32(acc[mf][nf], ah[mf], bl[nf]);
                        mma_tf32(acc[mf][nf], al[mf], bh[nf]);
                    }
                }
        }

        if (it + 1 < nk) storeTile((it + 1) & 1);
        __syncthreads();
    }

    #pragma unroll
    for (int mf = 0; mf < 2; mf++) {
        const int r0 = m0 + wm * 32 + 16 * mf + g;
        #pragma unroll
        for (int nf = 0; nf < NF; nf++) {
            const int c = n0 + wn * (BN / 2) + 8 * nf + 2 * tid;
            *(float2*)(Cp + (long)r0 * ldc + c)       = make_float2(acc[mf][nf][0], acc[mf][nf][1]);
            *(float2*)(Cp + (long)(r0 + 8) * ldc + c) = make_float2(acc[mf][nf][2], acc[mf][nf][3]);
        }
    }
}

// Split-K partial reduction (float4-wide)
__global__ __launch_bounds__(256)
void reduce_add(const float* __restrict__ src, float* __restrict__ dst,
                int n4, int parts, long pstride4)
{
    int i = blockIdx.x * blockDim.x + threadIdx.x;
    if (i >= n4) return;
    const float4* s = (const float4*)src;
    float4 acc = s[i];
    for (int p = 1; p < parts; p++) {
        float4 v = s[i + (long)p * pstride4];
        acc.x += v.x; acc.y += v.y; acc.z += v.z; acc.w += v.w;
    }
    ((float4*)dst)[i] = acc;
}

// ===========================================================================
// Tiny fp32-exact precompute kernels (unchanged)
// ===========================================================================
__global__ __launch_bounds__(128)
void pk_kernel(const float* __restrict__ W_uq, const float* __restrict__ W_uk,
               float* __restrict__ P)
{
    const int i = blockIdx.x, j = threadIdx.x;
    float s = 0.f;
    #pragma unroll 8
    for (int c = 0; c < 1024; c++)
        s += W_uq[c * 128 + i] * W_uk[c * 128 + j];
    P[i * 128 + j] = s;
}
__global__ __launch_bounds__(128)
void m_kernel(const float* __restrict__ W_dq, const float* __restrict__ P,
              float* __restrict__ M)
{
    const int c = blockIdx.x, j = threadIdx.x;
    float s = 0.f;
    #pragma unroll 8
    for (int i = 0; i < 128; i++)
        s += W_dq[i * 1024 + c] * P[i * 128 + j];
    M[c * 128 + j] = s;
}
__global__ __launch_bounds__(128)
void n_kernel(const float* __restrict__ W_uq, const float* __restrict__ M,
              float* __restrict__ Nt)
{
    const int j = blockIdx.x, h = blockIdx.y, i = threadIdx.x;
    float s = 0.f;
    #pragma unroll 8
    for (int d = 0; d < 64; d++)
        s += W_uq[(h * 64 + d) * 128 + i] * M[(h * 64 + d) * 128 + j];
    Nt[(h * 128 + j) * 128 + i] = s;
}

// ===========================================================================
// fp16 mma flash attention v6.
// 64 q x 128-key tiles (halves per-key sync/rescale/shuffle overhead);
// REGISTER-RESIDENT P: the S C-fragment layout == PV A-fragment layout for
// m16n8k16 (cols 8nb+2tid+j == 16kb+2tid+j for nb=2kb), so P never touches
// smem -- pack sacc pairs with f2h2 directly into PV A-frags.
// K1: [s=128][d half2, stride 68]  - S-phase B, conflict-free.
// KT: [d=128][s half2, stride 69]  - PV B, near-conflict-free.
// 70 KB smem, 128 thr, 2 CTAs/SM.
// ===========================================================================
#define A6_K1 0                        // 128 x 68 words
#define A6_KT (128 * 68)               // 128 x 69 words
#define A6_WORDS (128 * 68 + 128 * 69) // 17536 words = 70144 B

__global__ __launch_bounds__(128, 2)
void attn6_kernel(const float* __restrict__ ql, const float* __restrict__ ckv,
                  float* __restrict__ ctx)
{
    extern __shared__ uint32_t smu[];
    const int t = threadIdx.x;
    const int w = t >> 5, lid = t & 31;
    const int g = lid >> 2, tid = lid & 3;

    const int h  = blockIdx.x;               // fastest: K-tile L2 sharing
    const int qt = 31 - blockIdx.y;          // heavy q-tiles first
    const int b  = blockIdx.z;
    const long qbase = ((long)h * BT + (long)b * Tt + (long)qt * 64) * 128;
    const long kbase = (long)b * Tt * 128;

    const int rl0 = 16 * w + g;              // local query row (0..63)
    const int nkt = (qt >> 1) + 1;           // 128-key tiles

    // ---- Q A-fragments (fp16, prescaled by 1/8) -> 32 registers ----
    uint32_t qf[8][4];
    {
        const float* qr0 = ql + qbase + (long)rl0 * 128;
        const float* qr1 = qr0 + 8 * 128;
        #pragma unroll
        for (int kb = 0; kb < 8; kb++) {
            const int c = 16 * kb + 2 * tid;
            float2 v00 = *(const float2*)(qr0 + c);
            float2 v10 = *(const float2*)(qr1 + c);
            float2 v01 = *(const float2*)(qr0 + c + 8);
            float2 v11 = *(const float2*)(qr1 + c + 8);
            qf[kb][0] = f2h2(v00.x * 0.125f, v00.y * 0.125f);
            qf[kb][1] = f2h2(v10.x * 0.125f, v10.y * 0.125f);
            qf[kb][2] = f2h2(v01.x * 0.125f, v01.y * 0.125f);
            qf[kb][3] = f2h2(v11.x * 0.125f, v11.y * 0.125f);
        }
    }

    float oacc[16][4];
    #pragma unroll
    for (int nb = 0; nb < 16; nb++)
        #pragma unroll
        for (int q = 0; q < 4; q++) oacc[nb][q] = 0.f;

    float m_run[2] = { -1e30f, -1e30f };
    float l_run[2] = { 0.f, 0.f };

    for (int kt = 0; kt < nkt; kt++) {
        __syncthreads();     // prev PV reads of K1/KT done before overwrite
        {
            const float* ks = ckv + kbase + (long)kt * 128 * 128;
            // K1: s-major half2 rows (128 rows x 32 float4 = 4096 quads)
            #pragma unroll
            for (int i = 0; i < 32; i++) {
                int idx = t + i * 128;
                int r = idx >> 5, c = (idx & 31) * 4;
                float4 v = *(const float4*)(ks + (long)r * 128 + c);
                uint2 u = make_uint2(f2h2(v.x, v.y), f2h2(v.z, v.w));
                *(uint2*)(smu + A6_K1 + r * 68 + (c >> 1)) = u;
            }
            // KT: d-major half2 (thread t owns column d = t)
            {
                const float* kc = ks + t;
                #pragma unroll
                for (int s = 0; s < 128; s += 4) {
                    float a0 = kc[(s + 0) * 128];
                    float a1 = kc[(s + 1) * 128];
                    float a2 = kc[(s + 2) * 128];
                    float a3 = kc[(s + 3) * 128];
                    smu[A6_KT + t * 69 + (s >> 1)]     = f2h2(a0, a1);
                    smu[A6_KT + t * 69 + (s >> 1) + 1] = f2h2(a2, a3);
                }
            }
        }
        __syncthreads();

        // ---- S = Q K^T : 8 f16 k-blocks (d) x 16 key-blocks ----
        float sacc[16][4];
        #pragma unroll
        for (int nb = 0; nb < 16; nb++)
            #pragma unroll
            for (int q = 0; q < 4; q++) sacc[nb][q] = 0.f;

        #pragma unroll
        for (int kb = 0; kb < 8; kb++) {
            const int w0 = 8 * kb + tid;
            #pragma unroll
            for (int nb = 0; nb < 16; nb++) {
                uint32_t b0 = smu[A6_K1 + (8 * nb + g) * 68 + w0];
                uint32_t b1 = smu[A6_K1 + (8 * nb + g) * 68 + w0 + 4];
                mma_f16(sacc[nb], qf[kb], b0, b1);
            }
        }

        // ---- causal mask (last tile only) ----
        if (kt == nkt - 1) {
            const int row0 = 64 * qt + rl0;
            #pragma unroll
            for (int nb = 0; nb < 16; nb++)
                #pragma unroll
                for (int j = 0; j < 2; j++) {
                    const int col = 128 * kt + 8 * nb + 2 * tid + j;
                    if (col > row0)     sacc[nb][j]     = -1e30f;
                    if (col > row0 + 8) sacc[nb][2 + j] = -1e30f;
                }
        }

        // ---- online softmax; P stays in sacc registers ----
        #pragma unroll
        for (int hh = 0; hh < 2; hh++) {
            float mt = -1e30f;
            #pragma unroll
            for (int nb = 0; nb < 16; nb++)
                mt = fmaxf(mt, fmaxf(sacc[nb][2 * hh], sacc[nb][2 * hh + 1]));
            mt = fmaxf(mt, __shfl_xor_sync(0xffffffffu, mt, 1));
            mt = fmaxf(mt, __shfl_xor_sync(0xffffffffu, mt, 2));

            const float mn = fmaxf(m_run[hh], mt);
            const float sc = __expf(m_run[hh] - mn);
            float ls = 0.f;
            #pragma unroll
            for (int nb = 0; nb < 16; nb++) {
                float p0 = __expf(sacc[nb][2 * hh]     - mn);
                float p1 = __expf(sacc[nb][2 * hh + 1] - mn);
                ls += p0 + p1;
                sacc[nb][2 * hh]     = p0;
                sacc[nb][2 * hh + 1] = p1;
            }
            ls += __shfl_xor_sync(0xffffffffu, ls, 1);
            ls += __shfl_xor_sync(0xffffffffu, ls, 2);
            l_run[hh] = l_run[hh] * sc + ls;
            m_run[hh] = mn;
            #pragma unroll
            for (int nb = 0; nb < 16; nb++) {
                oacc[nb][2 * hh]     *= sc;
                oacc[nb][2 * hh + 1] *= sc;
            }
        }

        // ---- O += P @ Ktile : P packed from sacc (register-resident) ----
        #pragma unroll
        for (int kb = 0; kb < 8; kb++) {
            uint32_t af[4];
            af[0] = f2h2(sacc[2 * kb][0],     sacc[2 * kb][1]);
            af[1] = f2h2(sacc[2 * kb][2],     sacc[2 * kb][3]);
            af[2] = f2h2(sacc[2 * kb + 1][0], sacc[2 * kb + 1][1]);
            af[3] = f2h2(sacc[2 * kb + 1][2], sacc[2 * kb + 1][3]);
            const int w0 = 8 * kb + tid;
            #pragma unroll
            for (int nb = 0; nb < 16; nb++) {
                uint32_t b0 = smu[A6_KT + (8 * nb + g) * 69 + w0];
                uint32_t b1 = smu[A6_KT + (8 * nb + g) * 69 + w0 + 4];
                mma_f16(oacc[nb], af, b0, b1);
            }
        }
    }

    // ---- epilogue: ctx = O / l ----
    #pragma unroll
    for (int hh = 0; hh < 2; hh++) {
        const int rl = rl0 + 8 * hh;
        const float inv = 1.f / l_run[hh];
        float* dst = ctx + qbase + (long)rl * 128;
        #pragma unroll
        for (int nb = 0; nb < 16; nb++)
            *(float2*)(dst + 8 * nb + 2 * tid) =
                make_float2(oacc[nb][2 * hh] * inv, oacc[nb][2 * hh + 1] * inv);
    }
}

// ===========================================================================
extern "C" void kernel_launch(void* const* d_in, const int* in_sizes, int n_in,
                              void* d_out, int out_size)
{
    const float* x     = (const float*)d_in[0];
    const float* W_dq  = (const float*)d_in[1];
    const float* W_uq  = (const float*)d_in[2];
    const float* W_dkv = (const float*)d_in[3];
    const float* W_uk  = (const float*)d_in[4];
    const float* W_uv  = (const float*)d_in[5];
    const float* W_o   = (const float*)d_in[6];

    float* y   = (float*)d_out;
    float* ckv = y + (long)BT * Cc;

    float *P, *M, *Nt, *R, *Aq, *QLp, *CT;
    cudaGetSymbolAddress((void**)&P,  g_P);
    cudaGetSymbolAddress((void**)&M,  g_M);
    cudaGetSymbolAddress((void**)&Nt, g_Nt);
    cudaGetSymbolAddress((void**)&R,  g_R);
    cudaGetSymbolAddress((void**)&Aq, g_Aq);
    cudaGetSymbolAddress((void**)&QLp, g_ql);
    cudaGetSymbolAddress((void**)&CT, g_ct);

    const int NONE = 1 << 30;
    const size_t S64   = 2 * (128 * 20 + 64 * 20) * 4;
    const size_t S128  = 2 * (128 * 20 + 128 * 20) * 4;
    const size_t S64C  = 2 * 2 * (128 * 20 + 64 * 20) * 4;

    cudaFuncSetAttribute((const void*)tgemm<64, false, true>,
                         cudaFuncAttributeMaxDynamicSharedMemorySize, (int)S64C);
    cudaFuncSetAttribute((const void*)tgemm<128, false, false>,
                         cudaFuncAttributeMaxDynamicSharedMemorySize, (int)S128);
    cudaFuncSetAttribute((const void*)tgemm<64, true, false>,
                         cudaFuncAttributeMaxDynamicSharedMemorySize, (int)S64);
    cudaFuncSetAttribute((const void*)tgemm<64, false, false>,
                         cudaFuncAttributeMaxDynamicSharedMemorySize, (int)S64);

    // Exact fp32 precompute chain: P -> M -> Nt
    pk_kernel<<<128, 128>>>(W_uq, W_uk, P);
    m_kernel<<<1024, 128>>>(W_dq, P, M);
    n_kernel<<<dim3(128, 16), 128>>>(W_uq, M, Nt);

    // Fused x-GEMM, split-K=2
    {
        const long PS = (long)BT * 128;
        tgemm<64, false, true><<<dim3(32, 4, 2), 256, S64C>>>(
            x, W_dq, CT, W_dkv, CT + 2 * PS, 512,
            1024, 1024, 128, 512, 512, PS, 2);
        reduce_add<<<512, 256>>>(CT,          Aq,  (int)(PS / 4), 2, PS / 4);
        reduce_add<<<512, 256>>>(CT + 2 * PS, ckv, (int)(PS / 4), 2, PS / 4);
    }

    // R = W_o @ W_uv, split-K=4
    {
        const long PR = 1024 * 128;
        tgemm<64, true, false><<<dim3(8, 2, 4), 256, S64>>>(
            W_o, W_uv, CT, nullptr, nullptr, 256,
            1024, 128, 128, 256, 256 * 128, PR, NONE);
        reduce_add<<<128, 256>>>(CT, R, (int)(PR / 4), 4, PR / 4);
    }

    // ql[h] = Aq @ N[h]   (batched 16, K=128)
    tgemm<128, false, false><<<dim3(32, 1, 16), 256, S128>>>(
        Aq, Nt, QLp, nullptr, nullptr, 128, 128, 128, 128,
        0, 128 * 128, (long)BT * 128, NONE);

    // fp16 flash attention v6 -> ctx
    cudaFuncSetAttribute(attn6_kernel, cudaFuncAttributeMaxDynamicSharedMemorySize,
                         A6_WORDS * 4);
    attn6_kernel<<<dim3(16, 32, 2), 128, A6_WORDS * 4>>>(QLp, ckv, CT);

    // y[:, h*64:] = ctx[h] @ R[h*64:, :]^T   (batched 16, K=128, N=64)
    tgemm<64, false, false><<<dim3(32, 1, 16), 256, S64>>>(
        CT, R, y, nullptr, nullptr, 128, 128, 128, 1024,
        (long)BT * 128, 64 * 128, 64, NONE);
}

// round 11
// speedup vs baseline: 2.1562x; 1.1009x over previous
#include <cuda_runtime.h>
#include <cuda_fp16.h>
#include <cstdint>

// Problem constants (fixed by setup_inputs)
#define Bb    2
#define Tt    2048
#define Cc    1024
#define QLd   128
#define KVL   128
#define NHh   16
#define HSd   64
#define BT    (Bb*Tt)          // 4096

// Scratch (device globals: no allocation allowed)
__device__ float g_P [QLd*KVL];
__device__ float g_M [Cc*KVL];
__device__ float g_Nt[NHh*KVL*QLd];
__device__ float g_R [Cc*KVL];
__device__ float g_Aq[BT*QLd];
__device__ float g_ql[NHh*BT*KVL];
__device__ float g_ct[NHh*BT*KVL];       // latent context (also GEMM partial scratch)
__device__ __half g_kh [Bb*Tt*KVL];      // ckv as fp16, s-major  [b][s][d]
__device__ __half g_khT[Bb*KVL*Tt];      // ckv as fp16, d-major  [b][d][s]

__device__ __forceinline__ uint32_t f2tf(float f) {
    uint32_t u;
    asm("cvt.rna.tf32.f32 %0, %1;" : "=r"(u) : "f"(f));
    return u;
}
__device__ __forceinline__ uint32_t f2h2(float a, float b) {
    __half2 h = __floats2half2_rn(a, b);
    return *(uint32_t*)&h;
}
__device__ __forceinline__ void mma_tf32(float* d, const uint32_t* a, const uint32_t* b) {
    asm volatile(
        "mma.sync.aligned.m16n8k8.row.col.f32.tf32.tf32.f32 "
        "{%0,%1,%2,%3}, {%4,%5,%6,%7}, {%8,%9}, {%0,%1,%2,%3};"
        : "+f"(d[0]), "+f"(d[1]), "+f"(d[2]), "+f"(d[3])
        : "r"(a[0]), "r"(a[1]), "r"(a[2]), "r"(a[3]), "r"(b[0]), "r"(b[1]));
}
__device__ __forceinline__ void mma_f16(float* d, const uint32_t* a, uint32_t b0, uint32_t b1) {
    asm volatile(
        "mma.sync.aligned.m16n8k16.row.col.f32.f16.f16.f32 "
        "{%0,%1,%2,%3}, {%4,%5,%6,%7}, {%8,%9}, {%0,%1,%2,%3};"
        : "+f"(d[0]), "+f"(d[1]), "+f"(d[2]), "+f"(d[3])
        : "r"(a[0]), "r"(a[1]), "r"(a[2]), "r"(a[3]), "r"(b0), "r"(b1));
}

// ===========================================================================
// tf32 tensor-core GEMM, software-pipelined (unchanged from R8-R10)
// ===========================================================================
template<int BN, bool NN, bool COMP>
__global__ __launch_bounds__(256)
void tgemm(const float* __restrict__ A, const float* __restrict__ B,
           float* __restrict__ C, const float* __restrict__ B2,
           float* __restrict__ C2, int K,
           int lda, int ldb, int ldc, long sA, long sB, long sC, int nb1)
{
    constexpr int BM = 128, AW = BM * 20, BW = BN * 20;
    constexpr int NF = BN / 16;
    constexpr int STG = (COMP ? 2 : 1) * (AW + BW);
    constexpr int NB64 = BN / 64;
    extern __shared__ uint32_t sh[];

    const int z = blockIdx.z;
    A += (long)z * sA;
    const float* Bp = B;  float* Cp = C;
    int by = blockIdx.y;
    if (by >= nb1) { Bp = B2; Cp = C2; by -= nb1; }
    Bp += (long)z * sB;  Cp += (long)z * sC;

    const int m0 = blockIdx.x * BM, n0 = by * BN;
    const int t = threadIdx.x;
    const int wid = t >> 5, g = (t & 31) >> 2, tid = t & 3;
    const int wm = wid >> 1, wn = wid & 1;

    float acc[2][NF][4];
    #pragma unroll
    for (int i = 0; i < 2; i++)
        #pragma unroll
        for (int j = 0; j < NF; j++)
            #pragma unroll
            for (int q = 0; q < 4; q++) acc[i][j][q] = 0.f;

    float4 aR[2], bR[NB64 > 0 ? NB64 : 1];

    auto loadTile = [&](int k0) {
        #pragma unroll
        for (int i = 0; i < 2; i++) {
            int idx = t + i * 256;
            int r = idx >> 2, cg = (idx & 3) * 4;
            aR[i] = *(const float4*)(A + (long)(m0 + r) * lda + k0 + cg);
        }
        if (!NN) {
            #pragma unroll
            for (int i = 0; i < NB64; i++) {
                int idx = t + i * 256;
                int r = idx >> 2, cg = (idx & 3) * 4;
                bR[i] = *(const float4*)(Bp + (long)(n0 + r) * ldb + k0 + cg);
            }
        } else {
            #pragma unroll
            for (int i = 0; i < NB64; i++) {
                int idx = t + i * 256;
                int kr = idx >> (BN == 64 ? 4 : 5);
                int nn = (idx & (BN / 4 - 1)) * 4;
                bR[i] = *(const float4*)(Bp + (long)(k0 + kr) * ldb + n0 + nn);
            }
        }
    };
    auto storeTile = [&](int s) {
        uint32_t* Ah = sh + s * STG;
        uint32_t* Bh = Ah + AW;
        uint32_t* Al = Bh + BW;
        uint32_t* Bl = Al + AW;
        #pragma unroll
        for (int i = 0; i < 2; i++) {
            int idx = t + i * 256;
            int r = idx >> 2, cg = (idx & 3) * 4;
            float4 v = aR[i];
            uint4 h; h.x = f2tf(v.x); h.y = f2tf(v.y); h.z = f2tf(v.z); h.w = f2tf(v.w);
            *(uint4*)(Ah + r * 20 + cg) = h;
            if (COMP) {
                uint4 l;
                l.x = f2tf(v.x - __uint_as_float(h.x));
                l.y = f2tf(v.y - __uint_as_float(h.y));
                l.z = f2tf(v.z - __uint_as_float(h.z));
                l.w = f2tf(v.w - __uint_as_float(h.w));
                *(uint4*)(Al + r * 20 + cg) = l;
            }
        }
        if (!NN) {
            #pragma unroll
            for (int i = 0; i < NB64; i++) {
                int idx = t + i * 256;
                int r = idx >> 2, cg = (idx & 3) * 4;
                float4 v = bR[i];
                uint4 h; h.x = f2tf(v.x); h.y = f2tf(v.y); h.z = f2tf(v.z); h.w = f2tf(v.w);
                *(uint4*)(Bh + r * 20 + cg) = h;
                if (COMP) {
                    uint4 l;
                    l.x = f2tf(v.x - __uint_as_float(h.x));
                    l.y = f2tf(v.y - __uint_as_float(h.y));
                    l.z = f2tf(v.z - __uint_as_float(h.z));
                    l.w = f2tf(v.w - __uint_as_float(h.w));
                    *(uint4*)(Bl + r * 20 + cg) = l;
                }
            }
        } else {
            #pragma unroll
            for (int i = 0; i < NB64; i++) {
                int idx = t + i * 256;
                int kr = idx >> (BN == 64 ? 4 : 5);
                int nn = (idx & (BN / 4 - 1)) * 4;
                float4 v = bR[i];
                Bh[(nn + 0) * 20 + kr] = f2tf(v.x);
                Bh[(nn + 1) * 20 + kr] = f2tf(v.y);
                Bh[(nn + 2) * 20 + kr] = f2tf(v.z);
                Bh[(nn + 3) * 20 + kr] = f2tf(v.w);
            }
        }
    };

    const int nk = K / 16;
    loadTile(0);
    storeTile(0);
    __syncthreads();

    for (int it = 0; it < nk; it++) {
        if (it + 1 < nk) loadTile(16 * (it + 1));

        const uint32_t* Ah = sh + (it & 1) * STG;
        const uint32_t* Bh = Ah + AW;
        const uint32_t* Al = Bh + BW;
        const uint32_t* Bl = Al + AW;

        #pragma unroll
        for (int s = 0; s < 2; s++) {
            const int kk = 8 * s + tid;
            uint32_t ah[2][4], al[2][4];
            #pragma unroll
            for (int mf = 0; mf < 2; mf++) {
                int r = wm * 32 + 16 * mf + g;
                ah[mf][0] = Ah[r * 20 + kk];       ah[mf][1] = Ah[(r + 8) * 20 + kk];
                ah[mf][2] = Ah[r * 20 + kk + 4];   ah[mf][3] = Ah[(r + 8) * 20 + kk + 4];
                if (COMP) {
                    al[mf][0] = Al[r * 20 + kk];     al[mf][1] = Al[(r + 8) * 20 + kk];
                    al[mf][2] = Al[r * 20 + kk + 4]; al[mf][3] = Al[(r + 8) * 20 + kk + 4];
                }
            }
            uint32_t bh[NF][2], bl[NF][2];
            #pragma unroll
            for (int nf = 0; nf < NF; nf++) {
                int n = wn * (BN / 2) + 8 * nf + g;
                bh[nf][0] = Bh[n * 20 + kk];  bh[nf][1] = Bh[n * 20 + kk + 4];
                if (COMP) { bl[nf][0] = Bl[n * 20 + kk]; bl[nf][1] = Bl[n * 20 + kk + 4]; }
            }
            #pragma unroll
            for (int mf = 0; mf < 2; mf++)
                #pragma unroll
                for (int nf = 0; nf < NF; nf++) {
                    mma_tf32(acc[mf][nf], ah[mf], bh[nf]);
                    if (COMP) {
                        mma_tf32(acc[mf][nf], ah[mf], bl[nf]);
                        mma_tf32(acc[mf][nf], al[mf], bh[nf]);
                    }
                }
        }

        if (it + 1 < nk) storeTile((it + 1) & 1);
        __syncthreads();
    }

    #pragma unroll
    for (int mf = 0; mf < 2; mf++) {
        const int r0 = m0 + wm * 32 + 16 * mf + g;
        #pragma unroll
        for (int nf = 0; nf < NF; nf++) {
            const int c = n0 + wn * (BN / 2) + 8 * nf + 2 * tid;
            *(float2*)(Cp + (long)r0 * ldc + c)       = make_float2(acc[mf][nf][0], acc[mf][nf][1]);
            *(float2*)(Cp + (long)(r0 + 8) * ldc + c) = make_float2(acc[mf][nf][2], acc[mf][nf][3]);
        }
    }
}

// Split-K partial reduction (float4-wide)
__global__ __launch_bounds__(256)
void reduce_add(const float* __restrict__ src, float* __restrict__ dst,
                int n4, int parts, long pstride4)
{
    int i = blockIdx.x * blockDim.x + threadIdx.x;
    if (i >= n4) return;
    const float4* s = (const float4*)src;
    float4 acc = s[i];
    for (int p = 1; p < parts; p++) {
        float4 v = s[i + (long)p * pstride4];
        acc.x += v.x; acc.y += v.y; acc.z += v.z; acc.w += v.w;
    }
    ((float4*)dst)[i] = acc;
}

// ===========================================================================
// ckv -> fp16 one-shot conversion, both layouts. One CTA per 128(s)x128(d)
// tile; smem transpose for the d-major output.
// ===========================================================================
__global__ __launch_bounds__(256)
void cvt_kernel(const float* __restrict__ ckv, __half* __restrict__ kh,
                __half* __restrict__ khT)
{
    __shared__ __half sm[128 * 132];
    const int st = blockIdx.x, b = blockIdx.y;
    const float* src = ckv + ((long)b * Tt + st * 128) * 128;
    __half* dsh = kh + ((long)b * Tt + st * 128) * 128;
    const int t = threadIdx.x;

    #pragma unroll
    for (int i = 0; i < 16; i++) {
        int idx = t + i * 256;
        int r = idx >> 5, c = (idx & 31) * 4;
        float4 v = *(const float4*)(src + (long)r * 128 + c);
        uint2 u = make_uint2(f2h2(v.x, v.y), f2h2(v.z, v.w));
        *(uint2*)(dsh + (long)r * 128 + c) = u;
        *(uint2*)(sm + r * 132 + c) = u;
    }
    __syncthreads();

    // transposed write: row d holds s-contiguous halves
    #pragma unroll
    for (int i = 0; i < 16; i++) {
        int idx = t + i * 256;
        int d = idx >> 5, sg = (idx & 31) * 4;
        __half h0 = sm[(sg + 0) * 132 + d];
        __half h1 = sm[(sg + 1) * 132 + d];
        __half h2 = sm[(sg + 2) * 132 + d];
        __half h3 = sm[(sg + 3) * 132 + d];
        uint2 u;
        __half2 p0 = __halves2half2(h0, h1);
        __half2 p1 = __halves2half2(h2, h3);
        u.x = *(uint32_t*)&p0;  u.y = *(uint32_t*)&p1;
        *(uint2*)(khT + ((long)b * 128 + d) * Tt + st * 128 + sg) = u;
    }
}

// ===========================================================================
// Tiny fp32-exact precompute kernels (unchanged)
// ===========================================================================
__global__ __launch_bounds__(128)
void pk_kernel(const float* __restrict__ W_uq, const float* __restrict__ W_uk,
               float* __restrict__ P)
{
    const int i = blockIdx.x, j = threadIdx.x;
    float s = 0.f;
    #pragma unroll 8
    for (int c = 0; c < 1024; c++)
        s += W_uq[c * 128 + i] * W_uk[c * 128 + j];
    P[i * 128 + j] = s;
}
__global__ __launch_bounds__(128)
void m_kernel(const float* __restrict__ W_dq, const float* __restrict__ P,
              float* __restrict__ M)
{
    const int c = blockIdx.x, j = threadIdx.x;
    float s = 0.f;
    #pragma unroll 8
    for (int i = 0; i < 128; i++)
        s += W_dq[i * 1024 + c] * P[i * 128 + j];
    M[c * 128 + j] = s;
}
__global__ __launch_bounds__(128)
void n_kernel(const float* __restrict__ W_uq, const float* __restrict__ M,
              float* __restrict__ Nt)
{
    const int j = blockIdx.x, h = blockIdx.y, i = threadIdx.x;
    float s = 0.f;
    #pragma unroll 8
    for (int d = 0; d < 64; d++)
        s += W_uq[(h * 64 + d) * 128 + i] * M[(h * 64 + d) * 128 + j];
    Nt[(h * 128 + j) * 128 + i] = s;
}

// ===========================================================================
// fp16 mma flash attention v7.
// Same compute structure as v6 (64q x 128k tiles, register-resident P), but
// K tiles stream from PRE-CONVERTED fp16 buffers in both layouts -- loaders
// are pure uint4 copies (16 LDG.128 + 16 STS.128 per thread per tile).
// Both smem tiles stride 68 words: MMA-phase bank map 4g+tid (conflict-free),
// STS.128 phases cover 32 distinct banks. 69.6 KB smem, 2 CTAs/SM.
// ===========================================================================
#define A7_K1 0                        // 128 x 68 words (s-major half2)
#define A7_KT (128 * 68)               // 128 x 68 words (d-major half2)
#define A7_WORDS (2 * 128 * 68)        // 17408 words = 69632 B

__global__ __launch_bounds__(128, 2)
void attn7_kernel(const float* __restrict__ ql, const __half* __restrict__ khG,
                  const __half* __restrict__ khTG, float* __restrict__ ctx)
{
    extern __shared__ uint32_t smu[];
    const int t = threadIdx.x;
    const int w = t >> 5, lid = t & 31;
    const int g = lid >> 2, tid = lid & 3;

    const int h  = blockIdx.x;               // fastest: K-tile L2 sharing
    const int qt = 31 - blockIdx.y;          // heavy q-tiles first
    const int b  = blockIdx.z;
    const long qbase = ((long)h * BT + (long)b * Tt + (long)qt * 64) * 128;

    const int rl0 = 16 * w + g;              // local query row (0..63)
    const int nkt = (qt >> 1) + 1;           // 128-key tiles

    // ---- Q A-fragments (fp16, prescaled by 1/8) -> 32 registers ----
    uint32_t qf[8][4];
    {
        const float* qr0 = ql + qbase + (long)rl0 * 128;
        const float* qr1 = qr0 + 8 * 128;
        #pragma unroll
        for (int kb = 0; kb < 8; kb++) {
            const int c = 16 * kb + 2 * tid;
            float2 v00 = *(const float2*)(qr0 + c);
            float2 v10 = *(const float2*)(qr1 + c);
            float2 v01 = *(const float2*)(qr0 + c + 8);
            float2 v11 = *(const float2*)(qr1 + c + 8);
            qf[kb][0] = f2h2(v00.x * 0.125f, v00.y * 0.125f);
            qf[kb][1] = f2h2(v10.x * 0.125f, v10.y * 0.125f);
            qf[kb][2] = f2h2(v01.x * 0.125f, v01.y * 0.125f);
            qf[kb][3] = f2h2(v11.x * 0.125f, v11.y * 0.125f);
        }
    }

    float oacc[16][4];
    #pragma unroll
    for (int nb = 0; nb < 16; nb++)
        #pragma unroll
        for (int q = 0; q < 4; q++) oacc[nb][q] = 0.f;

    float m_run[2] = { -1e30f, -1e30f };
    float l_run[2] = { 0.f, 0.f };

    for (int kt = 0; kt < nkt; kt++) {
        __syncthreads();     // prev PV reads done before overwrite
        {
            const __half* kh  = khG  + ((long)b * Tt + (long)kt * 128) * 128;
            const __half* khT = khTG + (long)b * 128 * Tt + (long)kt * 128;
            #pragma unroll
            for (int i = 0; i < 16; i++) {
                int idx = t + i * 128;
                int r = idx >> 4, c = idx & 15;
                *(uint4*)(smu + A7_K1 + r * 68 + c * 4) =
                    *(const uint4*)(kh + (long)r * 128 + c * 8);
            }
            #pragma unroll
            for (int i = 0; i < 16; i++) {
                int idx = t + i * 128;
                int d = idx >> 4, c = idx & 15;
                *(uint4*)(smu + A7_KT + d * 68 + c * 4) =
                    *(const uint4*)(khT + (long)d * Tt + c * 8);
            }
        }
        __syncthreads();

        // ---- S = Q K^T : 8 f16 k-blocks (d) x 16 key-blocks ----
        float sacc[16][4];
        #pragma unroll
        for (int nb = 0; nb < 16; nb++)
            #pragma unroll
            for (int q = 0; q < 4; q++) sacc[nb][q] = 0.f;

        #pragma unroll
        for (int kb = 0; kb < 8; kb++) {
            const int w0 = 8 * kb + tid;
            #pragma unroll
            for (int nb = 0; nb < 16; nb++) {
                uint32_t b0 = smu[A7_K1 + (8 * nb + g) * 68 + w0];
                uint32_t b1 = smu[A7_K1 + (8 * nb + g) * 68 + w0 + 4];
                mma_f16(sacc[nb], qf[kb], b0, b1);
            }
        }

        // ---- causal mask (last tile only) ----
        if (kt == nkt - 1) {
            const int row0 = 64 * qt + rl0;
            #pragma unroll
            for (int nb = 0; nb < 16; nb++)
                #pragma unroll
                for (int j = 0; j < 2; j++) {
                    const int col = 128 * kt + 8 * nb + 2 * tid + j;
                    if (col > row0)     sacc[nb][j]     = -1e30f;
                    if (col > row0 + 8) sacc[nb][2 + j] = -1e30f;
                }
        }

        // ---- online softmax; P stays in sacc registers ----
        #pragma unroll
        for (int hh = 0; hh < 2; hh++) {
            float mt = -1e30f;
            #pragma unroll
            for (int nb = 0; nb < 16; nb++)
                mt = fmaxf(mt, fmaxf(sacc[nb][2 * hh], sacc[nb][2 * hh + 1]));
            mt = fmaxf(mt, __shfl_xor_sync(0xffffffffu, mt, 1));
            mt = fmaxf(mt, __shfl_xor_sync(0xffffffffu, mt, 2));

            const float mn = fmaxf(m_run[hh], mt);
            const float sc = __expf(m_run[hh] - mn);
            float ls = 0.f;
            #pragma unroll
            for (int nb = 0; nb < 16; nb++) {
                float p0 = __expf(sacc[nb][2 * hh]     - mn);
                float p1 = __expf(sacc[nb][2 * hh + 1] - mn);
                ls += p0 + p1;
                sacc[nb][2 * hh]     = p0;
                sacc[nb][2 * hh + 1] = p1;
            }
            ls += __shfl_xor_sync(0xffffffffu, ls, 1);
            ls += __shfl_xor_sync(0xffffffffu, ls, 2);
            l_run[hh] = l_run[hh] * sc + ls;
            m_run[hh] = mn;
            #pragma unroll
            for (int nb = 0; nb < 16; nb++) {
                oacc[nb][2 * hh]     *= sc;
                oacc[nb][2 * hh + 1] *= sc;
            }
        }

        // ---- O += P @ Ktile : P packed from sacc (register-resident) ----
        #pragma unroll
        for (int kb = 0; kb < 8; kb++) {
            uint32_t af[4];
            af[0] = f2h2(sacc[2 * kb][0],     sacc[2 * kb][1]);
            af[1] = f2h2(sacc[2 * kb][2],     sacc[2 * kb][3]);
            af[2] = f2h2(sacc[2 * kb + 1][0], sacc[2 * kb + 1][1]);
            af[3] = f2h2(sacc[2 * kb + 1][2], sacc[2 * kb + 1][3]);
            const int w0 = 8 * kb + tid;
            #pragma unroll
            for (int nb = 0; nb < 16; nb++) {
                uint32_t b0 = smu[A7_KT + (8 * nb + g) * 68 + w0];
                uint32_t b1 = smu[A7_KT + (8 * nb + g) * 68 + w0 + 4];
                mma_f16(oacc[nb], af, b0, b1);
            }
        }
    }

    // ---- epilogue: ctx = O / l ----
    #pragma unroll
    for (int hh = 0; hh < 2; hh++) {
        const int rl = rl0 + 8 * hh;
        const float inv = 1.f / l_run[hh];
        float* dst = ctx + qbase + (long)rl * 128;
        #pragma unroll
        for (int nb = 0; nb < 16; nb++)
            *(float2*)(dst + 8 * nb + 2 * tid) =
                make_float2(oacc[nb][2 * hh] * inv, oacc[nb][2 * hh + 1] * inv);
    }
}

// ===========================================================================
extern "C" void kernel_launch(void* const* d_in, const int* in_sizes, int n_in,
                              void* d_out, int out_size)
{
    const float* x     = (const float*)d_in[0];
    const float* W_dq  = (const float*)d_in[1];
    const float* W_uq  = (const float*)d_in[2];
    const float* W_dkv = (const float*)d_in[3];
    const float* W_uk  = (const float*)d_in[4];
    const float* W_uv  = (const float*)d_in[5];
    const float* W_o   = (const float*)d_in[6];

    float* y   = (float*)d_out;
    float* ckv = y + (long)BT * Cc;

    float *P, *M, *Nt, *R, *Aq, *QLp, *CT;
    __half *KH, *KHT;
    cudaGetSymbolAddress((void**)&P,  g_P);
    cudaGetSymbolAddress((void**)&M,  g_M);
    cudaGetSymbolAddress((void**)&Nt, g_Nt);
    cudaGetSymbolAddress((void**)&R,  g_R);
    cudaGetSymbolAddress((void**)&Aq, g_Aq);
    cudaGetSymbolAddress((void**)&QLp, g_ql);
    cudaGetSymbolAddress((void**)&CT, g_ct);
    cudaGetSymbolAddress((void**)&KH,  g_kh);
    cudaGetSymbolAddress((void**)&KHT, g_khT);

    const int NONE = 1 << 30;
    const size_t S64   = 2 * (128 * 20 + 64 * 20) * 4;
    const size_t S128  = 2 * (128 * 20 + 128 * 20) * 4;
    const size_t S64C  = 2 * 2 * (128 * 20 + 64 * 20) * 4;

    cudaFuncSetAttribute((const void*)tgemm<64, false, true>,
                         cudaFuncAttributeMaxDynamicSharedMemorySize, (int)S64C);
    cudaFuncSetAttribute((const void*)tgemm<128, false, false>,
                         cudaFuncAttributeMaxDynamicSharedMemorySize, (int)S128);
    cudaFuncSetAttribute((const void*)tgemm<64, true, false>,
                         cudaFuncAttributeMaxDynamicSharedMemorySize, (int)S64);
    cudaFuncSetAttribute((const void*)tgemm<64, false, false>,
                         cudaFuncAttributeMaxDynamicSharedMemorySize, (int)S64);

    // Exact fp32 precompute chain: P -> M -> Nt
    pk_kernel<<<128, 128>>>(W_uq, W_uk, P);
    m_kernel<<<1024, 128>>>(W_dq, P, M);
    n_kernel<<<dim3(128, 16), 128>>>(W_uq, M, Nt);

    // Fused x-GEMM, split-K=2
    {
        const long PS = (long)BT * 128;
        tgemm<64, false, true><<<dim3(32, 4, 2), 256, S64C>>>(
            x, W_dq, CT, W_dkv, CT + 2 * PS, 512,
            1024, 1024, 128, 512, 512, PS, 2);
        reduce_add<<<512, 256>>>(CT,          Aq,  (int)(PS / 4), 2, PS / 4);
        reduce_add<<<512, 256>>>(CT + 2 * PS, ckv, (int)(PS / 4), 2, PS / 4);
    }

    // ckv -> fp16 (both layouts), one-shot
    cvt_kernel<<<dim3(16, 2), 256>>>(ckv, KH, KHT);

    // R = W_o @ W_uv, split-K=4
    {
        const long PR = 1024 * 128;
        tgemm<64, true, false><<<dim3(8, 2, 4), 256, S64>>>(
            W_o, W_uv, CT, nullptr, nullptr, 256,
            1024, 128, 128, 256, 256 * 128, PR, NONE);
        reduce_add<<<128, 256>>>(CT, R, (int)(PR / 4), 4, PR / 4);
    }

    // ql[h] = Aq @ N[h]   (batched 16, K=128)
    tgemm<128, false, false><<<dim3(32, 1, 16), 256, S128>>>(
        Aq, Nt, QLp, nullptr, nullptr, 128, 128, 128, 128,
        0, 128 * 128, (long)BT * 128, NONE);

    // fp16 flash attention v7 -> ctx
    cudaFuncSetAttribute(attn7_kernel, cudaFuncAttributeMaxDynamicSharedMemorySize,
                         A7_WORDS * 4);
    attn7_kernel<<<dim3(16, 32, 2), 128, A7_WORDS * 4>>>(QLp, KH, KHT, CT);

    // y[:, h*64:] = ctx[h] @ R[h*64:, :]^T   (batched 16, K=128, N=64)
    tgemm<64, false, false><<<dim3(32, 1, 16), 256, S64>>>(
        CT, R, y, nullptr, nullptr, 128, 128, 128, 1024,
        (long)BT * 128, 64 * 128, 64, NONE);
}

// round 12
// speedup vs baseline: 2.4423x; 1.1327x over previous
#include <cuda_runtime.h>
#include <cuda_fp16.h>
#include <cstdint>

// Problem constants (fixed by setup_inputs)
#define Bb    2
#define Tt    2048
#define Cc    1024
#define QLd   128
#define KVL   128
#define NHh   16
#define HSd   64
#define BT    (Bb*Tt)          // 4096

// Scratch (device globals: no allocation allowed)
__device__ float g_P [QLd*KVL];
__device__ float g_M [Cc*KVL];
__device__ float g_Nt[NHh*KVL*QLd];
__device__ float g_R [Cc*KVL];
__device__ float g_Aq[BT*QLd];
__device__ float g_ql[NHh*BT*KVL];
__device__ float g_ct[NHh*BT*KVL];       // latent context (also GEMM partial scratch)
__device__ __half g_kh [Bb*Tt*KVL];      // ckv as fp16, s-major  [b][s][d]
__device__ __half g_khT[Bb*KVL*Tt];      // ckv as fp16, d-major  [b][d][s]

__device__ __forceinline__ uint32_t f2h2(float a, float b) {
    __half2 h = __floats2half2_rn(a, b);
    return *(uint32_t*)&h;
}
__device__ __forceinline__ void mma_f16(float* d, const uint32_t* a, uint32_t b0, uint32_t b1) {
    asm volatile(
        "mma.sync.aligned.m16n8k16.row.col.f32.f16.f16.f32 "
        "{%0,%1,%2,%3}, {%4,%5,%6,%7}, {%8,%9}, {%0,%1,%2,%3};"
        : "+f"(d[0]), "+f"(d[1]), "+f"(d[2]), "+f"(d[3])
        : "r"(a[0]), "r"(a[1]), "r"(a[2]), "r"(a[3]), "r"(b0), "r"(b1));
}

// ===========================================================================
// fp16 tensor-core GEMM, software-pipelined, double-buffered.
// BM=128, BK=32 (2 x m16n8k16 k-steps per tile), 256 thr, warps 4(m) x 2(n).
// Smem rows: 16 half2 words + pad -> stride 20 words (bank maps verified).
// COMP: hi/lo fp16 split with lo pre-scaled by 1024 (separate accumulator,
// epilogue C = accH + accL/1024) -> ~22-bit products, protects ckv.
// Batch axis z doubles as split-K axis via sA/sB/sC.
// ===========================================================================
template<int BN, bool NN, bool COMP>
__global__ __launch_bounds__(256)
void hgemm(const float* __restrict__ A, const float* __restrict__ B,
           float* __restrict__ C, const float* __restrict__ B2,
           float* __restrict__ C2, int K,
           int lda, int ldb, int ldc, long sA, long sB, long sC, int nb1)
{
    constexpr int BM = 128, AW = BM * 20, BW = BN * 20;
    constexpr int NF = BN / 16;
    constexpr int STG = (COMP ? 2 : 1) * (AW + BW);
    constexpr int NA4 = BM * 8 / 256;          // A float4 per thread = 4
    constexpr int NB4 = BN * 8 / 256;          // B float4 per thread
    extern __shared__ uint32_t sh[];

    const int z = blockIdx.z;
    A += (long)z * sA;
    const float* Bp = B;  float* Cp = C;
    int by = blockIdx.y;
    if (by >= nb1) { Bp = B2; Cp = C2; by -= nb1; }
    Bp += (long)z * sB;  Cp += (long)z * sC;

    const int m0 = blockIdx.x * BM, n0 = by * BN;
    const int t = threadIdx.x;
    const int wid = t >> 5, g = (t & 31) >> 2, tid = t & 3;
    const int wm = wid >> 1, wn = wid & 1;

    float accH[2][NF][4];
    float accL[COMP ? 2 : 1][COMP ? NF : 1][4];
    #pragma unroll
    for (int i = 0; i < 2; i++)
        #pragma unroll
        for (int j = 0; j < NF; j++)
            #pragma unroll
            for (int q = 0; q < 4; q++) {
                accH[i][j][q] = 0.f;
                if (COMP) accL[i][j][q] = 0.f;
            }

    float4 aR[NA4], bR[NB4];

    auto loadTile = [&](int k0) {
        #pragma unroll
        for (int i = 0; i < NA4; i++) {
            int idx = t + i * 256;
            int r = idx >> 3, c4 = (idx & 7) * 4;
            aR[i] = *(const float4*)(A + (long)(m0 + r) * lda + k0 + c4);
        }
        if (!NN) {
            #pragma unroll
            for (int i = 0; i < NB4; i++) {
                int idx = t + i * 256;
                int r = idx >> 3, c4 = (idx & 7) * 4;
                bR[i] = *(const float4*)(Bp + (long)(n0 + r) * ldb + k0 + c4);
            }
        } else {
            #pragma unroll
            for (int i = 0; i < NB4; i++) {
                int idx = t + i * 256;
                int kr = idx / (BN / 4);
                int nn = (idx % (BN / 4)) * 4;
                bR[i] = *(const float4*)(Bp + (long)(k0 + kr) * ldb + n0 + nn);
            }
        }
    };
    auto storeTile = [&](int s) {
        uint32_t* Ah = sh + s * STG;
        uint32_t* Bh = Ah + AW;
        uint32_t* Al = Bh + BW;
        uint32_t* Bl = Al + AW;
        #pragma unroll
        for (int i = 0; i < NA4; i++) {
            int idx = t + i * 256;
            int r = idx >> 3, c4 = (idx & 7) * 4;
            float4 v = aR[i];
            uint32_t h0 = f2h2(v.x, v.y), h1 = f2h2(v.z, v.w);
            Ah[r * 20 + (c4 >> 1)]     = h0;
            Ah[r * 20 + (c4 >> 1) + 1] = h1;
            if (COMP) {
                __half2 p0 = *(__half2*)&h0, p1 = *(__half2*)&h1;
                float2 f0 = __half22float2(p0), f1 = __half22float2(p1);
                Al[r * 20 + (c4 >> 1)]     = f2h2((v.x - f0.x) * 1024.f, (v.y - f0.y) * 1024.f);
                Al[r * 20 + (c4 >> 1) + 1] = f2h2((v.z - f1.x) * 1024.f, (v.w - f1.y) * 1024.f);
            }
        }
        if (!NN) {
            #pragma unroll
            for (int i = 0; i < NB4; i++) {
                int idx = t + i * 256;
                int r = idx >> 3, c4 = (idx & 7) * 4;
                float4 v = bR[i];
                uint32_t h0 = f2h2(v.x, v.y), h1 = f2h2(v.z, v.w);
                Bh[r * 20 + (c4 >> 1)]     = h0;
                Bh[r * 20 + (c4 >> 1) + 1] = h1;
                if (COMP) {
                    __half2 p0 = *(__half2*)&h0, p1 = *(__half2*)&h1;
                    float2 f0 = __half22float2(p0), f1 = __half22float2(p1);
                    Bl[r * 20 + (c4 >> 1)]     = f2h2((v.x - f0.x) * 1024.f, (v.y - f0.y) * 1024.f);
                    Bl[r * 20 + (c4 >> 1) + 1] = f2h2((v.z - f1.x) * 1024.f, (v.w - f1.y) * 1024.f);
                }
            }
        } else {
            __half* Bhh = (__half*)Bh;
            #pragma unroll
            for (int i = 0; i < NB4; i++) {
                int idx = t + i * 256;
                int kr = idx / (BN / 4);
                int nn = (idx % (BN / 4)) * 4;
                float4 v = bR[i];
                Bhh[(nn + 0) * 40 + kr] = __float2half_rn(v.x);
                Bhh[(nn + 1) * 40 + kr] = __float2half_rn(v.y);
                Bhh[(nn + 2) * 40 + kr] = __float2half_rn(v.z);
                Bhh[(nn + 3) * 40 + kr] = __float2half_rn(v.w);
            }
        }
    };

    const int nk = K / 32;
    loadTile(0);
    storeTile(0);
    __syncthreads();

    for (int it = 0; it < nk; it++) {
        if (it + 1 < nk) loadTile(32 * (it + 1));

        const uint32_t* Ah = sh + (it & 1) * STG;
        const uint32_t* Bh = Ah + AW;
        const uint32_t* Al = Bh + BW;
        const uint32_t* Bl = Al + AW;

        #pragma unroll
        for (int s = 0; s < 2; s++) {
            const int kk = 8 * s + tid;
            uint32_t ah[2][4], al[2][4];
            #pragma unroll
            for (int mf = 0; mf < 2; mf++) {
                int r = wm * 32 + 16 * mf + g;
                ah[mf][0] = Ah[r * 20 + kk];       ah[mf][1] = Ah[(r + 8) * 20 + kk];
                ah[mf][2] = Ah[r * 20 + kk + 4];   ah[mf][3] = Ah[(r + 8) * 20 + kk + 4];
                if (COMP) {
                    al[mf][0] = Al[r * 20 + kk];     al[mf][1] = Al[(r + 8) * 20 + kk];
                    al[mf][2] = Al[r * 20 + kk + 4]; al[mf][3] = Al[(r + 8) * 20 + kk + 4];
                }
            }
            #pragma unroll
            for (int nf = 0; nf < NF; nf++) {
                int n = wn * (BN / 2) + 8 * nf + g;
                uint32_t b0 = Bh[n * 20 + kk], b1 = Bh[n * 20 + kk + 4];
                #pragma unroll
                for (int mf = 0; mf < 2; mf++) {
                    mma_f16(accH[mf][nf], ah[mf], b0, b1);
                    if (COMP) mma_f16(accL[mf][nf], al[mf], b0, b1);
                }
                if (COMP) {
                    uint32_t c0 = Bl[n * 20 + kk], c1 = Bl[n * 20 + kk + 4];
                    #pragma unroll
                    for (int mf = 0; mf < 2; mf++)
                        mma_f16(accL[mf][nf], ah[mf], c0, c1);
                }
            }
        }

        if (it + 1 < nk) storeTile((it + 1) & 1);
        __syncthreads();
    }

    const float lsc = 1.f / 1024.f;
    #pragma unroll
    for (int mf = 0; mf < 2; mf++) {
        const int r0 = m0 + wm * 32 + 16 * mf + g;
        #pragma unroll
        for (int nf = 0; nf < NF; nf++) {
            const int c = n0 + wn * (BN / 2) + 8 * nf + 2 * tid;
            float v0 = accH[mf][nf][0], v1 = accH[mf][nf][1];
            float v2 = accH[mf][nf][2], v3 = accH[mf][nf][3];
            if (COMP) {
                v0 += accL[mf][nf][0] * lsc;  v1 += accL[mf][nf][1] * lsc;
                v2 += accL[mf][nf][2] * lsc;  v3 += accL[mf][nf][3] * lsc;
            }
            *(float2*)(Cp + (long)r0 * ldc + c)       = make_float2(v0, v1);
            *(float2*)(Cp + (long)(r0 + 8) * ldc + c) = make_float2(v2, v3);
        }
    }
}

// Split-K partial reduction (float4-wide)
__global__ __launch_bounds__(256)
void reduce_add(const float* __restrict__ src, float* __restrict__ dst,
                int n4, int parts, long pstride4)
{
    int i = blockIdx.x * blockDim.x + threadIdx.x;
    if (i >= n4) return;
    const float4* s = (const float4*)src;
    float4 acc = s[i];
    for (int p = 1; p < parts; p++) {
        float4 v = s[i + (long)p * pstride4];
        acc.x += v.x; acc.y += v.y; acc.z += v.z; acc.w += v.w;
    }
    ((float4*)dst)[i] = acc;
}

// ===========================================================================
// ckv -> fp16 one-shot conversion, both layouts (unchanged from R11)
// ===========================================================================
__global__ __launch_bounds__(256)
void cvt_kernel(const float* __restrict__ ckv, __half* __restrict__ kh,
                __half* __restrict__ khT)
{
    __shared__ __half sm[128 * 132];
    const int st = blockIdx.x, b = blockIdx.y;
    const float* src = ckv + ((long)b * Tt + st * 128) * 128;
    __half* dsh = kh + ((long)b * Tt + st * 128) * 128;
    const int t = threadIdx.x;

    #pragma unroll
    for (int i = 0; i < 16; i++) {
        int idx = t + i * 256;
        int r = idx >> 5, c = (idx & 31) * 4;
        float4 v = *(const float4*)(src + (long)r * 128 + c);
        uint2 u = make_uint2(f2h2(v.x, v.y), f2h2(v.z, v.w));
        *(uint2*)(dsh + (long)r * 128 + c) = u;
        *(uint2*)(sm + r * 132 + c) = u;
    }
    __syncthreads();

    #pragma unroll
    for (int i = 0; i < 16; i++) {
        int idx = t + i * 256;
        int d = idx >> 5, sg = (idx & 31) * 4;
        __half h0 = sm[(sg + 0) * 132 + d];
        __half h1 = sm[(sg + 1) * 132 + d];
        __half h2 = sm[(sg + 2) * 132 + d];
        __half h3 = sm[(sg + 3) * 132 + d];
        uint2 u;
        __half2 p0 = __halves2half2(h0, h1);
        __half2 p1 = __halves2half2(h2, h3);
        u.x = *(uint32_t*)&p0;  u.y = *(uint32_t*)&p1;
        *(uint2*)(khT + ((long)b * 128 + d) * Tt + st * 128 + sg) = u;
    }
}

// ===========================================================================
// Tiny fp32-exact precompute kernels (unchanged)
// ===========================================================================
__global__ __launch_bounds__(128)
void pk_kernel(const float* __restrict__ W_uq, const float* __restrict__ W_uk,
               float* __restrict__ P)
{
    const int i = blockIdx.x, j = threadIdx.x;
    float s = 0.f;
    #pragma unroll 8
    for (int c = 0; c < 1024; c++)
        s += W_uq[c * 128 + i] * W_uk[c * 128 + j];
    P[i * 128 + j] = s;
}
__global__ __launch_bounds__(128)
void m_kernel(const float* __restrict__ W_dq, const float* __restrict__ P,
              float* __restrict__ M)
{
    const int c = blockIdx.x, j = threadIdx.x;
    float s = 0.f;
    #pragma unroll 8
    for (int i = 0; i < 128; i++)
        s += W_dq[i * 1024 + c] * P[i * 128 + j];
    M[c * 128 + j] = s;
}
__global__ __launch_bounds__(128)
void n_kernel(const float* __restrict__ W_uq, const float* __restrict__ M,
              float* __restrict__ Nt)
{
    const int j = blockIdx.x, h = blockIdx.y, i = threadIdx.x;
    float s = 0.f;
    #pragma unroll 8
    for (int d = 0; d < 64; d++)
        s += W_uq[(h * 64 + d) * 128 + i] * M[(h * 64 + d) * 128 + j];
    Nt[(h * 128 + j) * 128 + i] = s;
}

// ===========================================================================
// fp16 mma flash attention v7 (unchanged from R11)
// ===========================================================================
#define A7_K1 0
#define A7_KT (128 * 68)
#define A7_WORDS (2 * 128 * 68)

__global__ __launch_bounds__(128, 2)
void attn7_kernel(const float* __restrict__ ql, const __half* __restrict__ khG,
                  const __half* __restrict__ khTG, float* __restrict__ ctx)
{
    extern __shared__ uint32_t smu[];
    const int t = threadIdx.x;
    const int w = t >> 5, lid = t & 31;
    const int g = lid >> 2, tid = lid & 3;

    const int h  = blockIdx.x;
    const int qt = 31 - blockIdx.y;
    const int b  = blockIdx.z;
    const long qbase = ((long)h * BT + (long)b * Tt + (long)qt * 64) * 128;

    const int rl0 = 16 * w + g;
    const int nkt = (qt >> 1) + 1;

    uint32_t qf[8][4];
    {
        const float* qr0 = ql + qbase + (long)rl0 * 128;
        const float* qr1 = qr0 + 8 * 128;
        #pragma unroll
        for (int kb = 0; kb < 8; kb++) {
            const int c = 16 * kb + 2 * tid;
            float2 v00 = *(const float2*)(qr0 + c);
            float2 v10 = *(const float2*)(qr1 + c);
            float2 v01 = *(const float2*)(qr0 + c + 8);
            float2 v11 = *(const float2*)(qr1 + c + 8);
            qf[kb][0] = f2h2(v00.x * 0.125f, v00.y * 0.125f);
            qf[kb][1] = f2h2(v10.x * 0.125f, v10.y * 0.125f);
            qf[kb][2] = f2h2(v01.x * 0.125f, v01.y * 0.125f);
            qf[kb][3] = f2h2(v11.x * 0.125f, v11.y * 0.125f);
        }
    }

    float oacc[16][4];
    #pragma unroll
    for (int nb = 0; nb < 16; nb++)
        #pragma unroll
        for (int q = 0; q < 4; q++) oacc[nb][q] = 0.f;

    float m_run[2] = { -1e30f, -1e30f };
    float l_run[2] = { 0.f, 0.f };

    for (int kt = 0; kt < nkt; kt++) {
        __syncthreads();
        {
            const __half* kh  = khG  + ((long)b * Tt + (long)kt * 128) * 128;
            const __half* khT = khTG + (long)b * 128 * Tt + (long)kt * 128;
            #pragma unroll
            for (int i = 0; i < 16; i++) {
                int idx = t + i * 128;
                int r = idx >> 4, c = idx & 15;
                *(uint4*)(smu + A7_K1 + r * 68 + c * 4) =
                    *(const uint4*)(kh + (long)r * 128 + c * 8);
            }
            #pragma unroll
            for (int i = 0; i < 16; i++) {
                int idx = t + i * 128;
                int d = idx >> 4, c = idx & 15;
                *(uint4*)(smu + A7_KT + d * 68 + c * 4) =
                    *(const uint4*)(khT + (long)d * Tt + c * 8);
            }
        }
        __syncthreads();

        float sacc[16][4];
        #pragma unroll
        for (int nb = 0; nb < 16; nb++)
            #pragma unroll
            for (int q = 0; q < 4; q++) sacc[nb][q] = 0.f;

        #pragma unroll
        for (int kb = 0; kb < 8; kb++) {
            const int w0 = 8 * kb + tid;
            #pragma unroll
            for (int nb = 0; nb < 16; nb++) {
                uint32_t b0 = smu[A7_K1 + (8 * nb + g) * 68 + w0];
                uint32_t b1 = smu[A7_K1 + (8 * nb + g) * 68 + w0 + 4];
                mma_f16(sacc[nb], qf[kb], b0, b1);
            }
        }

        if (kt == nkt - 1) {
            const int row0 = 64 * qt + rl0;
            #pragma unroll
            for (int nb = 0; nb < 16; nb++)
                #pragma unroll
                for (int j = 0; j < 2; j++) {
                    const int col = 128 * kt + 8 * nb + 2 * tid + j;
                    if (col > row0)     sacc[nb][j]     = -1e30f;
                    if (col > row0 + 8) sacc[nb][2 + j] = -1e30f;
                }
        }

        #pragma unroll
        for (int hh = 0; hh < 2; hh++) {
            float mt = -1e30f;
            #pragma unroll
            for (int nb = 0; nb < 16; nb++)
                mt = fmaxf(mt, fmaxf(sacc[nb][2 * hh], sacc[nb][2 * hh + 1]));
            mt = fmaxf(mt, __shfl_xor_sync(0xffffffffu, mt, 1));
            mt = fmaxf(mt, __shfl_xor_sync(0xffffffffu, mt, 2));

            const float mn = fmaxf(m_run[hh], mt);
            const float sc = __expf(m_run[hh] - mn);
            float ls = 0.f;
            #pragma unroll
            for (int nb = 0; nb < 16; nb++) {
                float p0 = __expf(sacc[nb][2 * hh]     - mn);
                float p1 = __expf(sacc[nb][2 * hh + 1] - mn);
                ls += p0 + p1;
                sacc[nb][2 * hh]     = p0;
                sacc[nb][2 * hh + 1] = p1;
            }
            ls += __shfl_xor_sync(0xffffffffu, ls, 1);
            ls += __shfl_xor_sync(0xffffffffu, ls, 2);
            l_run[hh] = l_run[hh] * sc + ls;
            m_run[hh] = mn;
            #pragma unroll
            for (int nb = 0; nb < 16; nb++) {
                oacc[nb][2 * hh]     *= sc;
                oacc[nb][2 * hh + 1] *= sc;
            }
        }

        #pragma unroll
        for (int kb = 0; kb < 8; kb++) {
            uint32_t af[4];
            af[0] = f2h2(sacc[2 * kb][0],     sacc[2 * kb][1]);
            af[1] = f2h2(sacc[2 * kb][2],     sacc[2 * kb][3]);
            af[2] = f2h2(sacc[2 * kb + 1][0], sacc[2 * kb + 1][1]);
            af[3] = f2h2(sacc[2 * kb + 1][2], sacc[2 * kb + 1][3]);
            const int w0 = 8 * kb + tid;
            #pragma unroll
            for (int nb = 0; nb < 16; nb++) {
                uint32_t b0 = smu[A7_KT + (8 * nb + g) * 68 + w0];
                uint32_t b1 = smu[A7_KT + (8 * nb + g) * 68 + w0 + 4];
                mma_f16(oacc[nb], af, b0, b1);
            }
        }
    }

    #pragma unroll
    for (int hh = 0; hh < 2; hh++) {
        const int rl = rl0 + 8 * hh;
        const float inv = 1.f / l_run[hh];
        float* dst = ctx + qbase + (long)rl * 128;
        #pragma unroll
        for (int nb = 0; nb < 16; nb++)
            *(float2*)(dst + 8 * nb + 2 * tid) =
                make_float2(oacc[nb][2 * hh] * inv, oacc[nb][2 * hh + 1] * inv);
    }
}

// ===========================================================================
extern "C" void kernel_launch(void* const* d_in, const int* in_sizes, int n_in,
                              void* d_out, int out_size)
{
    const float* x     = (const float*)d_in[0];
    const float* W_dq  = (const float*)d_in[1];
    const float* W_uq  = (const float*)d_in[2];
    const float* W_dkv = (const float*)d_in[3];
    const float* W_uk  = (const float*)d_in[4];
    const float* W_uv  = (const float*)d_in[5];
    const float* W_o   = (const float*)d_in[6];

    float* y   = (float*)d_out;
    float* ckv = y + (long)BT * Cc;

    float *P, *M, *Nt, *R, *Aq, *QLp, *CT;
    __half *KH, *KHT;
    cudaGetSymbolAddress((void**)&P,  g_P);
    cudaGetSymbolAddress((void**)&M,  g_M);
    cudaGetSymbolAddress((void**)&Nt, g_Nt);
    cudaGetSymbolAddress((void**)&R,  g_R);
    cudaGetSymbolAddress((void**)&Aq, g_Aq);
    cudaGetSymbolAddress((void**)&QLp, g_ql);
    cudaGetSymbolAddress((void**)&CT, g_ct);
    cudaGetSymbolAddress((void**)&KH,  g_kh);
    cudaGetSymbolAddress((void**)&KHT, g_khT);

    const int NONE = 1 << 30;
    const size_t S64   = 2 * (128 * 20 + 64 * 20) * 4;        // 30720
    const size_t S128  = 2 * (128 * 20 + 128 * 20) * 4;       // 40960
    const size_t S64C  = 2 * 2 * (128 * 20 + 64 * 20) * 4;    // 61440

    cudaFuncSetAttribute((const void*)hgemm<64, false, true>,
                         cudaFuncAttributeMaxDynamicSharedMemorySize, (int)S64C);
    cudaFuncSetAttribute((const void*)hgemm<128, false, false>,
                         cudaFuncAttributeMaxDynamicSharedMemorySize, (int)S128);
    cudaFuncSetAttribute((const void*)hgemm<64, true, false>,
                         cudaFuncAttributeMaxDynamicSharedMemorySize, (int)S64);
    cudaFuncSetAttribute((const void*)hgemm<64, false, false>,
                         cudaFuncAttributeMaxDynamicSharedMemorySize, (int)S64);

    // Exact fp32 precompute chain: P -> M -> Nt
    pk_kernel<<<128, 128>>>(W_uq, W_uk, P);
    m_kernel<<<1024, 128>>>(W_dq, P, M);
    n_kernel<<<dim3(128, 16), 128>>>(W_uq, M, Nt);

    // Fused x-GEMM (fp16 compensated), split-K=2
    {
        const long PS = (long)BT * 128;
        hgemm<64, false, true><<<dim3(32, 4, 2), 256, S64C>>>(
            x, W_dq, CT, W_dkv, CT + 2 * PS, 512,
            1024, 1024, 128, 512, 512, PS, 2);
        reduce_add<<<512, 256>>>(CT,          Aq,  (int)(PS / 4), 2, PS / 4);
        reduce_add<<<512, 256>>>(CT + 2 * PS, ckv, (int)(PS / 4), 2, PS / 4);
    }

    // ckv -> fp16 (both layouts), one-shot
    cvt_kernel<<<dim3(16, 2), 256>>>(ckv, KH, KHT);

    // R = W_o @ W_uv (fp16 NN), split-K=4
    {
        const long PR = 1024 * 128;
        hgemm<64, true, false><<<dim3(8, 2, 4), 256, S64>>>(
            W_o, W_uv, CT, nullptr, nullptr, 256,
            1024, 128, 128, 256, 256 * 128, PR, NONE);
        reduce_add<<<128, 256>>>(CT, R, (int)(PR / 4), 4, PR / 4);
    }

    // ql[h] = Aq @ N[h]   (fp16, batched 16, K=128)
    hgemm<128, false, false><<<dim3(32, 1, 16), 256, S128>>>(
        Aq, Nt, QLp, nullptr, nullptr, 128, 128, 128, 128,
        0, 128 * 128, (long)BT * 128, NONE);

    // fp16 flash attention v7 -> ctx
    cudaFuncSetAttribute(attn7_kernel, cudaFuncAttributeMaxDynamicSharedMemorySize,
                         A7_WORDS * 4);
    attn7_kernel<<<dim3(16, 32, 2), 128, A7_WORDS * 4>>>(QLp, KH, KHT, CT);

    // y[:, h*64:] = ctx[h] @ R[h*64:, :]^T   (fp16, batched 16, K=128, N=64)
    hgemm<64, false, false><<<dim3(32, 1, 16), 256, S64>>>(
        CT, R, y, nullptr, nullptr, 128, 128, 128, 1024,
        (long)BT * 128, 64 * 128, 64, NONE);
}